// round 4
// baseline (speedup 1.0000x reference)
#include <cuda_runtime.h>
#include <math.h>

#define BB   64
#define LL   512
#define CC   256
#define HH   8
#define DHH  32
#define NTOK (BB*LL)

// ---------------- scratch (static __device__, no allocations) ----------------
__device__ float g_s1[(size_t)NTOK*CC];       // scorer hidden
__device__ float g_z[BB*LL];                  // raw scores
__device__ float g_sv[BB*LL];                 // y_soft values (jax-replicated)
__device__ unsigned char g_tier2[BB*LL];      // token_mask == 1-2^-24 flag
__device__ int   g_kper[BB];
__device__ int   g_kmax;
__device__ int   g_topk[BB*LL];
__device__ float g_hc[(size_t)NTOK*CC];       // h_compact (zero padded)
__device__ float g_qkv[(size_t)NTOK*3*CC];
__device__ float g_ao[(size_t)NTOK*CC];       // attention out pre-Wout
__device__ float g_hattn[(size_t)NTOK*CC];
__device__ float g_h[(size_t)NTOK*CC];        // residual-scaled hidden
__device__ float g_mid[(size_t)NTOK*2*CC];    // MLP hidden

// ---------------- generic GEMM: out = act(A[M,K] @ W[N,K]^T + bias) (+res) ---
template<int ACT, int RES>
__global__ __launch_bounds__(256)
void gemm_kernel(const float* __restrict__ A, const float* __restrict__ W,
                 const float* __restrict__ bias, const float* __restrict__ res,
                 float* __restrict__ out, int M, int N, int K)
{
    __shared__ float As[8][132];
    __shared__ float Bs[8][132];
    const int tid = threadIdx.x;
    const int tx = tid & 15, ty = tid >> 4;
    const int bm = blockIdx.y << 7, bn = blockIdx.x << 7;
    const int lr = tid >> 1;
    const int lc = (tid & 1) << 2;

    float acc[8][8];
#pragma unroll
    for (int i = 0; i < 8; i++)
#pragma unroll
        for (int j = 0; j < 8; j++) acc[i][j] = 0.f;

    const float* Ap = A + (size_t)(bm + lr) * K + lc;
    const float* Wp = W + (size_t)(bn + lr) * K + lc;

    for (int k0 = 0; k0 < K; k0 += 8) {
        float4 av = *(const float4*)(Ap + k0);
        float4 wv = *(const float4*)(Wp + k0);
        __syncthreads();
        As[lc+0][lr]=av.x; As[lc+1][lr]=av.y; As[lc+2][lr]=av.z; As[lc+3][lr]=av.w;
        Bs[lc+0][lr]=wv.x; Bs[lc+1][lr]=wv.y; Bs[lc+2][lr]=wv.z; Bs[lc+3][lr]=wv.w;
        __syncthreads();
#pragma unroll
        for (int kk = 0; kk < 8; kk++) {
            float a[8], b[8];
            *(float4*)&a[0] = *(const float4*)&As[kk][ty*8];
            *(float4*)&a[4] = *(const float4*)&As[kk][ty*8+4];
            *(float4*)&b[0] = *(const float4*)&Bs[kk][tx*8];
            *(float4*)&b[4] = *(const float4*)&Bs[kk][tx*8+4];
#pragma unroll
            for (int i = 0; i < 8; i++)
#pragma unroll
                for (int j = 0; j < 8; j++)
                    acc[i][j] = fmaf(a[i], b[j], acc[i][j]);
        }
    }

#pragma unroll
    for (int i = 0; i < 8; i++) {
        const size_t m = (size_t)bm + ty*8 + i;
#pragma unroll
        for (int j4 = 0; j4 < 2; j4++) {
            const int n = bn + tx*8 + j4*4;
            float v[4];
#pragma unroll
            for (int j = 0; j < 4; j++) {
                float t = acc[i][j4*4+j] + bias[n+j];
                if (ACT) t = fmaxf(t, 0.f);
                if (RES) t += res[m*N + n + j];
                v[j] = t;
            }
            *(float4*)(out + m*N + n) = make_float4(v[0],v[1],v[2],v[3]);
        }
    }
}

// ---------------- raw scores: z[n] = s1[n]·Ws2 + bs2 --------------------------
__global__ __launch_bounds__(256)
void score_kernel(const float* __restrict__ Ws2, const float* __restrict__ bs2)
{
    int gid  = blockIdx.x * 256 + threadIdx.x;
    int n    = gid >> 5;
    int lane = gid & 31;
    const float4* r4 = (const float4*)(g_s1 + (size_t)n * CC);
    const float4* w4 = (const float4*)Ws2;
    float4 a0 = r4[lane*2],   b0 = w4[lane*2];
    float4 a1 = r4[lane*2+1], b1 = w4[lane*2+1];
    float s = a0.x*b0.x + a0.y*b0.y + a0.z*b0.z + a0.w*b0.w
            + a1.x*b1.x + a1.y*b1.y + a1.z*b1.z + a1.w*b1.w;
#pragma unroll
    for (int o = 16; o; o >>= 1) s += __shfl_down_sync(0xffffffffu, s, o);
    if (lane == 0) g_z[n] = s + bs2[0];
}

// ---------------- jax-replicated softmax pipeline + tier flag -----------------
// ls = (scores - m1) - log(sum exp(scores - m1)); z = ls + gumbel
// s  = exp(z - m2) / sum exp(z - m2)
// tier2 = ( fl(fl(1+s) - s) != 1 )   [token_mask residue]
__global__ __launch_bounds__(512)
void softmax_kernel(const float* __restrict__ gumbel)
{
    __shared__ float red[512];
    const int b = blockIdx.x, t = threadIdx.x;
    const int n = b * 512 + t;
    float sc = g_z[n];

    red[t] = sc; __syncthreads();
#pragma unroll
    for (int s = 256; s; s >>= 1) { if (t < s) red[t] = fmaxf(red[t], red[t+s]); __syncthreads(); }
    float m1 = red[0]; __syncthreads();

    float sh = __fadd_rn(sc, -m1);
    float e1 = expf(sh);
    red[t] = e1; __syncthreads();
#pragma unroll
    for (int s = 256; s; s >>= 1) { if (t < s) red[t] = __fadd_rn(red[t], red[t+s]); __syncthreads(); }
    float L = logf(red[0]); __syncthreads();

    float ls = __fadd_rn(sh, -L);
    float z  = __fadd_rn(ls, gumbel[n]);
    red[t] = z; __syncthreads();
#pragma unroll
    for (int s = 256; s; s >>= 1) { if (t < s) red[t] = fmaxf(red[t], red[t+s]); __syncthreads(); }
    float m2 = red[0]; __syncthreads();

    float e2 = expf(__fadd_rn(z, -m2));
    red[t] = e2; __syncthreads();
#pragma unroll
    for (int s = 256; s; s >>= 1) { if (t < s) red[t] = __fadd_rn(red[t], red[t+s]); __syncthreads(); }
    float S = red[0];

    float sval = __fdiv_rn(e2, S);
    g_sv[n] = sval;
    float tt = __fadd_rn(__fadd_rn(1.0f, sval), -sval);
    g_tier2[n] = (tt != 1.0f) ? 1 : 0;
}

// ---------------- k_per / k_max ----------------------------------------------
__global__ void kper_kernel(const float* __restrict__ ratio)
{
    __shared__ int sm[64];
    int b = threadIdx.x;
    int kp = (int)ceilf(ratio[b] * 512.0f);
    if (kp < 1)  kp = 1;
    if (kp > LL) kp = LL;
    g_kper[b] = kp;
    sm[b] = kp;
    __syncthreads();
    for (int s = 32; s > 0; s >>= 1) {
        if (b < s) sm[b] = max(sm[b], sm[b+s]);
        __syncthreads();
    }
    if (b == 0) g_kmax = sm[0];
}

// ---------------- per-batch selection: sort by (y_soft desc, idx asc), --------
// kept = first kper of (tier1 by idx, then tier2 by idx) among top-kmax --------
__global__ __launch_bounds__(512)
void topk_kernel()
{
    __shared__ float sv[512];
    __shared__ int   si[512];
    __shared__ int   sfl[512];   // selected flag by node index
    __shared__ int   sA[512];    // packed scans
    const int b = blockIdx.x, t = threadIdx.x;
    sv[t] = g_sv[b*512 + t];
    si[t] = t;
    __syncthreads();
    // bitonic sort: (value desc, index asc)
    for (int k = 2; k <= 512; k <<= 1) {
        for (int j = k >> 1; j > 0; j >>= 1) {
            int ixj = t ^ j;
            if (ixj > t) {
                bool desc = ((t & k) == 0);
                float v1 = sv[t], v2 = sv[ixj];
                int   i1 = si[t], i2 = si[ixj];
                bool less = (v1 < v2) || (v1 == v2 && i1 > i2);
                bool sw = desc ? less : !less;
                if (sw) {
                    sv[t] = v2; sv[ixj] = v1;
                    si[t] = i2; si[ixj] = i1;
                }
            }
            __syncthreads();
        }
    }
    const int kmax = g_kmax;
    const int kper = g_kper[b];
    sfl[si[t]] = (t < kmax) ? 1 : 0;
    __syncthreads();
    const int sel   = sfl[t];
    const int tier2 = (int)g_tier2[b*512 + t];
    const int a1 = sel & (tier2 ^ 1);
    const int a2 = sel & tier2;
    sA[t] = a1 | (a2 << 16);
    __syncthreads();
    for (int off = 1; off < 512; off <<= 1) {          // inclusive scan
        int add = (t >= off) ? sA[t-off] : 0;
        __syncthreads();
        sA[t] += add;
        __syncthreads();
    }
    const int inc1 = sA[t] & 0xffff, inc2 = sA[t] >> 16;
    const int n1   = sA[511] & 0xffff;                 // total selected tier-1
    const int excl1 = inc1 - a1, excl2 = inc2 - a2;
    const int kept = (a1 && excl1 < kper) || (a2 && (n1 + excl2) < kper);
    const int nk = 1 - kept;
    __syncthreads();
    sA[t] = kept | (nk << 16);
    __syncthreads();
    for (int off = 1; off < 512; off <<= 1) {
        int add = (t >= off) ? sA[t-off] : 0;
        __syncthreads();
        sA[t] += add;
        __syncthreads();
    }
    const int rk = (sA[t] & 0xffff) - kept;
    const int rn = (sA[t] >> 16) - nk;
    if (kept) g_topk[b*512 + rk] = t;                  // kept set (ascending idx)
    else      g_topk[b*512 + kper + rn] = t;           // padding (ascending idx)
}

// ---------------- gather: h_compact[b,j,:] -----------------------------------
__global__ __launch_bounds__(64)
void gather_kernel(const float* __restrict__ x)
{
    int row = blockIdx.x;
    int b = row >> 9, j = row & 511;
    int t = threadIdx.x;
    float4* dst = (float4*)(g_hc + (size_t)row * CC);
    if (j < g_kper[b]) {
        int src = g_topk[row];
        const float4* s = (const float4*)(x + ((size_t)b*512 + src) * CC);
        dst[t] = s[t];
    } else {
        dst[t] = make_float4(0.f, 0.f, 0.f, 0.f);
    }
}

// ---------------- flash attention (fp32 SIMT), 2 queries/thread --------------
__global__ __launch_bounds__(128)
void attn_kernel()
{
    __shared__ float Ks[16][DHH];
    __shared__ float Vs[16][DHH];
    const int bh = blockIdx.x;
    const int b = bh >> 3, h = bh & 7;
    const int t = threadIdx.x;
    const int q0 = blockIdx.y << 8;
    const int kper = g_kper[b];
    const size_t base = (size_t)b * 512;
    const size_t hoff = (size_t)h * DHH;
    const int qi0 = q0 + t, qi1 = q0 + 128 + t;

    float q[2][DHH], acc[2][DHH];
    {
        const float4* qp0 = (const float4*)(g_qkv + (base + qi0) * 768 + hoff);
        const float4* qp1 = (const float4*)(g_qkv + (base + qi1) * 768 + hoff);
#pragma unroll
        for (int d4 = 0; d4 < 8; d4++) {
            float4 v0 = qp0[d4], v1 = qp1[d4];
            q[0][d4*4+0]=v0.x; q[0][d4*4+1]=v0.y; q[0][d4*4+2]=v0.z; q[0][d4*4+3]=v0.w;
            q[1][d4*4+0]=v1.x; q[1][d4*4+1]=v1.y; q[1][d4*4+2]=v1.z; q[1][d4*4+3]=v1.w;
        }
    }
#pragma unroll
    for (int u = 0; u < 2; u++)
#pragma unroll
        for (int d = 0; d < DHH; d++) acc[u][d] = 0.f;

    float m0 = -1e30f, m1 = -1e30f, l0 = 0.f, l1 = 0.f;
    const float scale = 0.17677669529663687f;   // 1/sqrt(32)
    const int lr  = t >> 3;
    const int lcc = (t & 7) << 2;

    for (int kt = 0; kt < kper; kt += 16) {
        const float* kp = g_qkv + (base + kt + lr) * 768 + 256 + hoff + lcc;
        float4 kv = *(const float4*)kp;
        float4 vv = *(const float4*)(kp + 256);
        __syncthreads();
        *(float4*)&Ks[lr][lcc] = kv;
        *(float4*)&Vs[lr][lcc] = vv;
        __syncthreads();

        const int jmax = min(16, kper - kt);
        float p0[16], p1[16];
        float mt0 = m0, mt1 = m1;
#pragma unroll
        for (int jj = 0; jj < 16; jj++) {
            if (jj < jmax) {
                float s0 = 0.f, s1 = 0.f;
#pragma unroll
                for (int d = 0; d < DHH; d++) {
                    float kd = Ks[jj][d];
                    s0 = fmaf(q[0][d], kd, s0);
                    s1 = fmaf(q[1][d], kd, s1);
                }
                s0 *= scale; s1 *= scale;
                p0[jj] = s0; p1[jj] = s1;
                mt0 = fmaxf(mt0, s0); mt1 = fmaxf(mt1, s1);
            } else { p0[jj] = -1e30f; p1[jj] = -1e30f; }
        }
        float sf0 = __expf(m0 - mt0), sf1 = __expf(m1 - mt1);
        l0 *= sf0; l1 *= sf1;
#pragma unroll
        for (int d = 0; d < DHH; d++) { acc[0][d] *= sf0; acc[1][d] *= sf1; }
        m0 = mt0; m1 = mt1;
#pragma unroll
        for (int jj = 0; jj < 16; jj++) {
            float e0 = __expf(p0[jj] - m0);
            float e1 = __expf(p1[jj] - m1);
            l0 += e0; l1 += e1;
#pragma unroll
            for (int d = 0; d < DHH; d++) {
                float vd = Vs[jj][d];
                acc[0][d] = fmaf(e0, vd, acc[0][d]);
                acc[1][d] = fmaf(e1, vd, acc[1][d]);
            }
        }
    }
    float inv0 = 1.f / l0, inv1 = 1.f / l1;
    float* o0 = g_ao + (base + qi0) * CC + hoff;
    float* o1 = g_ao + (base + qi1) * CC + hoff;
#pragma unroll
    for (int d4 = 0; d4 < 8; d4++) {
        *(float4*)(o0 + d4*4) = make_float4(acc[0][d4*4]*inv0, acc[0][d4*4+1]*inv0,
                                            acc[0][d4*4+2]*inv0, acc[0][d4*4+3]*inv0);
        *(float4*)(o1 + d4*4) = make_float4(acc[1][d4*4]*inv1, acc[1][d4*4+1]*inv1,
                                            acc[1][d4*4+2]*inv1, acc[1][d4*4+3]*inv1);
    }
}

// ---------------- h = x * ratio (base) ----------------------------------------
__global__ __launch_bounds__(256)
void hbase_kernel(const float* __restrict__ x, const float* __restrict__ ratio)
{
    int i = blockIdx.x * 256 + threadIdx.x;   // float4 index
    int b = i >> 15;                           // 32768 float4 per batch
    float r = ratio[b];
    float4 v = ((const float4*)x)[i];
    ((float4*)g_h)[i] = make_float4(v.x*r, v.y*r, v.z*r, v.w*r);
}

// ---------------- scatter h_attn back + residual + scale ----------------------
__global__ __launch_bounds__(64)
void scatter_kernel(const float* __restrict__ x, const float* __restrict__ ratio)
{
    int row = blockIdx.x;
    int b = row >> 9, j = row & 511;
    if (j >= g_kmax) return;
    int dst = g_topk[row];
    size_t n = (size_t)b * 512 + dst;
    float r = ratio[b];
    int t = threadIdx.x;
    float4 ha = ((const float4*)(g_hattn + (size_t)row * CC))[t];
    float4 xv = ((const float4*)(x + n * CC))[t];
    ((float4*)(g_h + n * CC))[t] =
        make_float4((ha.x+xv.x)*r, (ha.y+xv.y)*r, (ha.z+xv.z)*r, (ha.w+xv.w)*r);
}

// ------------------------------------------------------------------------------
extern "C" void kernel_launch(void* const* d_in, const int* in_sizes, int n_in,
                              void* d_out, int out_size)
{
    (void)in_sizes; (void)n_in; (void)out_size;
    const float* x      = (const float*)d_in[0];
    // d_in[1] edge_index unused (conv=None); d_in[2] batch structural
    const float* ratio  = (const float*)d_in[3];
    const float* gumbel = (const float*)d_in[4];
    const float* Ws1    = (const float*)d_in[5];
    const float* bs1    = (const float*)d_in[6];
    const float* Ws2    = (const float*)d_in[7];
    const float* bs2    = (const float*)d_in[8];
    const float* Win    = (const float*)d_in[9];
    const float* b_in   = (const float*)d_in[10];
    const float* Wout   = (const float*)d_in[11];
    const float* bout   = (const float*)d_in[12];
    const float* Wm1    = (const float*)d_in[13];
    const float* bm1    = (const float*)d_in[14];
    const float* Wm2    = (const float*)d_in[15];
    const float* bm2    = (const float*)d_in[16];
    float* out = (float*)d_out;

    float *s1p, *hcp, *qkvp, *aop, *hattnp, *hp, *midp;
    cudaGetSymbolAddress((void**)&s1p,    g_s1);
    cudaGetSymbolAddress((void**)&hcp,    g_hc);
    cudaGetSymbolAddress((void**)&qkvp,   g_qkv);
    cudaGetSymbolAddress((void**)&aop,    g_ao);
    cudaGetSymbolAddress((void**)&hattnp, g_hattn);
    cudaGetSymbolAddress((void**)&hp,     g_h);
    cudaGetSymbolAddress((void**)&midp,   g_mid);

    // 1. scorer hidden: s1 = relu(x @ Ws1^T + bs1)
    gemm_kernel<1,0><<<dim3(CC/128, NTOK/128), 256>>>(x, Ws1, bs1, nullptr, s1p, NTOK, CC, CC);
    // 2. raw scores
    score_kernel<<<NTOK/8, 256>>>(Ws2, bs2);
    // 3. jax-replicated softmax chain + tier flags
    softmax_kernel<<<BB, 512>>>(gumbel);
    // 4. k_per, k_max
    kper_kernel<<<1, 64>>>(ratio);
    // 5. per-batch selection -> g_topk (tier-aware kept set)
    topk_kernel<<<BB, 512>>>();
    // 6. h_compact gather (zero-padded)
    gather_kernel<<<NTOK, 64>>>(x);
    // 7. qkv = h_compact @ Win^T + b_in
    gemm_kernel<0,0><<<dim3(768/128, NTOK/128), 256>>>(hcp, Win, b_in, nullptr, qkvp, NTOK, 3*CC, CC);
    // 8. masked attention
    attn_kernel<<<dim3(BB*HH, 2), 128>>>();
    // 9. h_attn = ao @ Wout^T + bout
    gemm_kernel<0,0><<<dim3(CC/128, NTOK/128), 256>>>(aop, Wout, bout, nullptr, hattnp, NTOK, CC, CC);
    // 10. h = x * ratio (base)
    hbase_kernel<<<(NTOK*CC/4)/256, 256>>>(x, ratio);
    // 11. scatter: h[topk] = (h_attn + x) * ratio
    scatter_kernel<<<NTOK, 64>>>(x, ratio);
    // 12. mid = relu(h @ Wm1^T + bm1)
    gemm_kernel<1,0><<<dim3(512/128, NTOK/128), 256>>>(hp, Wm1, bm1, nullptr, midp, NTOK, 2*CC, CC);
    // 13. out = h + mid @ Wm2^T + bm2
    gemm_kernel<0,1><<<dim3(CC/128, NTOK/128), 256>>>(midp, Wm2, bm2, hp, out, NTOK, CC, 2*CC);
}

// round 7
// speedup vs baseline: 1.9578x; 1.9578x over previous
#include <cuda_runtime.h>
#include <cuda_bf16.h>
#include <math.h>
#include <stdint.h>

#define BB   64
#define LL   512
#define CC   256
#define HH   8
#define DHH  32
#define NTOK (BB*LL)

// ---------------- scratch (static __device__, no allocations) ----------------
__device__ float g_s1[(size_t)NTOK*CC];       // scorer hidden (fp32)
__device__ float g_z[BB*LL];                  // raw scores
__device__ float g_sv[BB*LL];                 // y_soft values (jax-replicated)
__device__ unsigned char g_tier2[BB*LL];      // token_mask residue flag
__device__ int   g_kper[BB];
__device__ int   g_kmax;
__device__ int   g_topk[BB*LL];
__device__ float g_qkv[(size_t)NTOK*3*CC];    // fp32 qkv (attention input)
__device__ float g_hattn[(size_t)NTOK*CC];    // fp32 Wout output
__device__ float g_h[(size_t)NTOK*CC];        // fp32 residual-scaled hidden
// bf16 operands for tensor-core GEMMs
__device__ __nv_bfloat16 g_hcb [(size_t)NTOK*CC];
__device__ __nv_bfloat16 g_aob [(size_t)NTOK*CC];
__device__ __nv_bfloat16 g_hb  [(size_t)NTOK*CC];
__device__ __nv_bfloat16 g_midb[(size_t)NTOK*2*CC];
__device__ __nv_bfloat16 g_Winb [3*CC*CC];
__device__ __nv_bfloat16 g_Woutb[CC*CC];
__device__ __nv_bfloat16 g_Wm1b [2*CC*CC];
__device__ __nv_bfloat16 g_Wm2b [CC*2*CC];

// ---------------- helpers -----------------------------------------------------
__device__ __forceinline__ uint32_t smem_u32(const void* p){
    uint32_t a;
    asm("{ .reg .u64 t; cvta.to.shared.u64 t, %1; cvt.u32.u64 %0, t; }" : "=r"(a) : "l"(p));
    return a;
}
__device__ __forceinline__ uint32_t pk(float a, float b){
    __nv_bfloat162 t = __floats2bfloat162_rn(a, b);
    return *reinterpret_cast<uint32_t*>(&t);
}
__device__ __forceinline__ void ldsm4(uint32_t& r0, uint32_t& r1, uint32_t& r2, uint32_t& r3,
                                      uint32_t addr){
    asm volatile("ldmatrix.sync.aligned.m8n8.x4.shared.b16 {%0,%1,%2,%3}, [%4];"
                 : "=r"(r0), "=r"(r1), "=r"(r2), "=r"(r3) : "r"(addr));
}
__device__ __forceinline__ void mma_bf16(float* c, const uint32_t* a, const uint32_t* b){
    asm volatile("mma.sync.aligned.m16n8k16.row.col.f32.bf16.bf16.f32 "
                 "{%0,%1,%2,%3}, {%4,%5,%6,%7}, {%8,%9}, {%0,%1,%2,%3};"
                 : "+f"(c[0]), "+f"(c[1]), "+f"(c[2]), "+f"(c[3])
                 : "r"(a[0]), "r"(a[1]), "r"(a[2]), "r"(a[3]), "r"(b[0]), "r"(b[1]));
}

// ---------------- warp-MMA bf16 GEMM: out = act(A@W^T + bias) (+res) ----------
// A[M,K] bf16 row-major, W[N,K] bf16 row-major (== col-major B for mma row.col).
// CTA tile 128x128, 8 warps (4 m x 2 n), each warp 32x64, BK=32. K % 32 == 0.
#define SROW 40   // smem row stride in bf16 (padded, 80B)

template<int ACT, int RES, int OUTBF>
__global__ __launch_bounds__(256)
void wmma_gemm(const __nv_bfloat16* __restrict__ A, const __nv_bfloat16* __restrict__ W,
               const float* __restrict__ bias, const float* __restrict__ res,
               float* __restrict__ outf, __nv_bfloat16* __restrict__ outb,
               int M, int N, int K)
{
    __shared__ __align__(16) __nv_bfloat16 As[128*SROW];
    __shared__ __align__(16) __nv_bfloat16 Bs[128*SROW];
    const uint32_t as_b = smem_u32(As);
    const uint32_t bs_b = smem_u32(Bs);
    const int tid  = threadIdx.x;
    const int wid  = tid >> 5, lane = tid & 31;
    const int bm   = blockIdx.y << 7;
    const int bn   = blockIdx.x << 7;
    const int wm   = wid & 3;        // warp m (32 rows)
    const int wn   = wid >> 2;       // warp n (64 cols)

    // global load mapping: 2 iterations, each thread one uint4 (8 bf16)
    const int lrow0 = (tid >> 2);          // 0..63
    const int lch   = (tid & 3) << 3;      // k element offset 0,8,16,24
    const __nv_bfloat16* Ap0 = A + (size_t)(bm + lrow0     ) * K + lch;
    const __nv_bfloat16* Ap1 = A + (size_t)(bm + lrow0 + 64) * K + lch;
    const __nv_bfloat16* Wp0 = W + (size_t)(bn + lrow0     ) * K + lch;
    const __nv_bfloat16* Wp1 = W + (size_t)(bn + lrow0 + 64) * K + lch;
    const uint32_t soff0 = (uint32_t)(lrow0      * SROW + lch) * 2;
    const uint32_t soff1 = (uint32_t)((lrow0+64) * SROW + lch) * 2;

    // ldmatrix addresses
    const uint32_t a_row = (uint32_t)(wm*32 + (lane & 15));
    const uint32_t a_kad = (uint32_t)((lane >> 4) << 3);
    const uint32_t b_row = (uint32_t)(wn*64 + ((lane >> 4) << 3) + (lane & 7));
    const uint32_t b_kad = (uint32_t)(((lane >> 3) & 1) << 3);

    float acc[2][8][4];
#pragma unroll
    for (int i = 0; i < 2; i++)
#pragma unroll
        for (int j = 0; j < 8; j++)
#pragma unroll
            for (int q = 0; q < 4; q++) acc[i][j][q] = 0.f;

    uint4 ra0 = *(const uint4*)Ap0, ra1 = *(const uint4*)Ap1;
    uint4 rb0 = *(const uint4*)Wp0, rb1 = *(const uint4*)Wp1;

    for (int k0 = 0; k0 < K; k0 += 32) {
        __syncthreads();
        asm volatile("st.shared.v4.b32 [%0], {%1,%2,%3,%4};"
                     :: "r"(as_b + soff0), "r"(ra0.x), "r"(ra0.y), "r"(ra0.z), "r"(ra0.w) : "memory");
        asm volatile("st.shared.v4.b32 [%0], {%1,%2,%3,%4};"
                     :: "r"(as_b + soff1), "r"(ra1.x), "r"(ra1.y), "r"(ra1.z), "r"(ra1.w) : "memory");
        asm volatile("st.shared.v4.b32 [%0], {%1,%2,%3,%4};"
                     :: "r"(bs_b + soff0), "r"(rb0.x), "r"(rb0.y), "r"(rb0.z), "r"(rb0.w) : "memory");
        asm volatile("st.shared.v4.b32 [%0], {%1,%2,%3,%4};"
                     :: "r"(bs_b + soff1), "r"(rb1.x), "r"(rb1.y), "r"(rb1.z), "r"(rb1.w) : "memory");
        __syncthreads();
        if (k0 + 32 < K) {
            ra0 = *(const uint4*)(Ap0 + k0 + 32); ra1 = *(const uint4*)(Ap1 + k0 + 32);
            rb0 = *(const uint4*)(Wp0 + k0 + 32); rb1 = *(const uint4*)(Wp1 + k0 + 32);
        }
#pragma unroll
        for (int ks = 0; ks < 2; ks++) {
            const uint32_t kcol = (uint32_t)(ks << 4);
            uint32_t a[2][4];
#pragma unroll
            for (int tm = 0; tm < 2; tm++) {
                uint32_t ad = as_b + ((a_row + tm*16) * SROW + kcol + a_kad) * 2;
                ldsm4(a[tm][0], a[tm][1], a[tm][2], a[tm][3], ad);
            }
            uint32_t b[8][2];
#pragma unroll
            for (int tp = 0; tp < 4; tp++) {
                uint32_t bd = bs_b + ((b_row + tp*16) * SROW + kcol + b_kad) * 2;
                ldsm4(b[2*tp][0], b[2*tp][1], b[2*tp+1][0], b[2*tp+1][1], bd);
            }
#pragma unroll
            for (int tm = 0; tm < 2; tm++)
#pragma unroll
                for (int tn = 0; tn < 8; tn++)
                    mma_bf16(acc[tm][tn], a[tm], b[tn]);
        }
    }

    // epilogue: d0,d1 -> row gm, cols gn,gn+1 ; d2,d3 -> row gm+8
#pragma unroll
    for (int tm = 0; tm < 2; tm++) {
        const int gm = bm + wm*32 + tm*16 + (lane >> 2);
#pragma unroll
        for (int tn = 0; tn < 8; tn++) {
            const int gn = bn + wn*64 + tn*8 + ((lane & 3) << 1);
            const float b0 = bias[gn], b1 = bias[gn+1];
#pragma unroll
            for (int half = 0; half < 2; half++) {
                const int m = gm + half*8;
                float v0 = acc[tm][tn][2*half+0] + b0;
                float v1 = acc[tm][tn][2*half+1] + b1;
                if (ACT) { v0 = fmaxf(v0, 0.f); v1 = fmaxf(v1, 0.f); }
                const size_t o = (size_t)m * N + gn;
                if (RES) {
                    float2 r = *(const float2*)(res + o);
                    v0 += r.x; v1 += r.y;
                }
                if (OUTBF) *(uint32_t*)(outb + o) = pk(v0, v1);
                else       *(float2*)(outf + o)   = make_float2(v0, v1);
            }
        }
    }
}

// ---------------- fp32 SIMT GEMM (scorer only — selection-critical) ----------
template<int ACT, int RES>
__global__ __launch_bounds__(256)
void gemm_kernel(const float* __restrict__ A, const float* __restrict__ W,
                 const float* __restrict__ bias, const float* __restrict__ res,
                 float* __restrict__ out, int M, int N, int K)
{
    __shared__ float As[8][132];
    __shared__ float Bs[8][132];
    const int tid = threadIdx.x;
    const int tx = tid & 15, ty = tid >> 4;
    const int bm = blockIdx.y << 7, bn = blockIdx.x << 7;
    const int lr = tid >> 1;
    const int lc = (tid & 1) << 2;

    float acc[8][8];
#pragma unroll
    for (int i = 0; i < 8; i++)
#pragma unroll
        for (int j = 0; j < 8; j++) acc[i][j] = 0.f;

    const float* Ap = A + (size_t)(bm + lr) * K + lc;
    const float* Wp = W + (size_t)(bn + lr) * K + lc;

    for (int k0 = 0; k0 < K; k0 += 8) {
        float4 av = *(const float4*)(Ap + k0);
        float4 wv = *(const float4*)(Wp + k0);
        __syncthreads();
        As[lc+0][lr]=av.x; As[lc+1][lr]=av.y; As[lc+2][lr]=av.z; As[lc+3][lr]=av.w;
        Bs[lc+0][lr]=wv.x; Bs[lc+1][lr]=wv.y; Bs[lc+2][lr]=wv.z; Bs[lc+3][lr]=wv.w;
        __syncthreads();
#pragma unroll
        for (int kk = 0; kk < 8; kk++) {
            float a[8], b[8];
            *(float4*)&a[0] = *(const float4*)&As[kk][ty*8];
            *(float4*)&a[4] = *(const float4*)&As[kk][ty*8+4];
            *(float4*)&b[0] = *(const float4*)&Bs[kk][tx*8];
            *(float4*)&b[4] = *(const float4*)&Bs[kk][tx*8+4];
#pragma unroll
            for (int i = 0; i < 8; i++)
#pragma unroll
                for (int j = 0; j < 8; j++)
                    acc[i][j] = fmaf(a[i], b[j], acc[i][j]);
        }
    }

#pragma unroll
    for (int i = 0; i < 8; i++) {
        const size_t m = (size_t)bm + ty*8 + i;
#pragma unroll
        for (int j4 = 0; j4 < 2; j4++) {
            const int n = bn + tx*8 + j4*4;
            float v[4];
#pragma unroll
            for (int j = 0; j < 4; j++) {
                float t = acc[i][j4*4+j] + bias[n+j];
                if (ACT) t = fmaxf(t, 0.f);
                if (RES) t += res[m*N + n + j];
                v[j] = t;
            }
            *(float4*)(out + m*N + n) = make_float4(v[0],v[1],v[2],v[3]);
        }
    }
}

// ---------------- weight fp32 -> bf16 ----------------------------------------
__global__ __launch_bounds__(256)
void f2bf_kernel(const float* __restrict__ s, __nv_bfloat16* __restrict__ d)
{
    int i = blockIdx.x * 256 + threadIdx.x;
    float4 v = ((const float4*)s)[i];
    uint2 p; p.x = pk(v.x, v.y); p.y = pk(v.z, v.w);
    ((uint2*)d)[i] = p;
}

// ---------------- raw scores: z[n] = s1[n]·Ws2 + bs2 --------------------------
__global__ __launch_bounds__(256)
void score_kernel(const float* __restrict__ Ws2, const float* __restrict__ bs2)
{
    int gid  = blockIdx.x * 256 + threadIdx.x;
    int n    = gid >> 5;
    int lane = gid & 31;
    const float4* r4 = (const float4*)(g_s1 + (size_t)n * CC);
    const float4* w4 = (const float4*)Ws2;
    float4 a0 = r4[lane*2],   b0 = w4[lane*2];
    float4 a1 = r4[lane*2+1], b1 = w4[lane*2+1];
    float s = a0.x*b0.x + a0.y*b0.y + a0.z*b0.z + a0.w*b0.w
            + a1.x*b1.x + a1.y*b1.y + a1.z*b1.z + a1.w*b1.w;
#pragma unroll
    for (int o = 16; o; o >>= 1) s += __shfl_down_sync(0xffffffffu, s, o);
    if (lane == 0) g_z[n] = s + bs2[0];
}

// ---------------- jax-replicated softmax pipeline + tier flag -----------------
__global__ __launch_bounds__(512)
void softmax_kernel(const float* __restrict__ gumbel)
{
    __shared__ float red[512];
    const int b = blockIdx.x, t = threadIdx.x;
    const int n = b * 512 + t;
    float sc = g_z[n];

    red[t] = sc; __syncthreads();
#pragma unroll
    for (int s = 256; s; s >>= 1) { if (t < s) red[t] = fmaxf(red[t], red[t+s]); __syncthreads(); }
    float m1 = red[0]; __syncthreads();

    float sh = __fadd_rn(sc, -m1);
    float e1 = expf(sh);
    red[t] = e1; __syncthreads();
#pragma unroll
    for (int s = 256; s; s >>= 1) { if (t < s) red[t] = __fadd_rn(red[t], red[t+s]); __syncthreads(); }
    float L = logf(red[0]); __syncthreads();

    float ls = __fadd_rn(sh, -L);
    float z  = __fadd_rn(ls, gumbel[n]);
    red[t] = z; __syncthreads();
#pragma unroll
    for (int s = 256; s; s >>= 1) { if (t < s) red[t] = fmaxf(red[t], red[t+s]); __syncthreads(); }
    float m2 = red[0]; __syncthreads();

    float e2 = expf(__fadd_rn(z, -m2));
    red[t] = e2; __syncthreads();
#pragma unroll
    for (int s = 256; s; s >>= 1) { if (t < s) red[t] = __fadd_rn(red[t], red[t+s]); __syncthreads(); }
    float S = red[0];

    float sval = __fdiv_rn(e2, S);
    g_sv[n] = sval;
    float tt = __fadd_rn(__fadd_rn(1.0f, sval), -sval);
    g_tier2[n] = (tt != 1.0f) ? 1 : 0;
}

// ---------------- k_per / k_max ----------------------------------------------
__global__ void kper_kernel(const float* __restrict__ ratio)
{
    __shared__ int sm[64];
    int b = threadIdx.x;
    int kp = (int)ceilf(ratio[b] * 512.0f);
    if (kp < 1)  kp = 1;
    if (kp > LL) kp = LL;
    g_kper[b] = kp;
    sm[b] = kp;
    __syncthreads();
    for (int s = 32; s > 0; s >>= 1) {
        if (b < s) sm[b] = max(sm[b], sm[b+s]);
        __syncthreads();
    }
    if (b == 0) g_kmax = sm[0];
}

// ---------------- per-batch selection (tier-aware, replicates reference) ------
__global__ __launch_bounds__(512)
void topk_kernel()
{
    __shared__ float sv[512];
    __shared__ int   si[512];
    __shared__ int   sfl[512];
    __shared__ int   sA[512];
    const int b = blockIdx.x, t = threadIdx.x;
    sv[t] = g_sv[b*512 + t];
    si[t] = t;
    __syncthreads();
    for (int k = 2; k <= 512; k <<= 1) {
        for (int j = k >> 1; j > 0; j >>= 1) {
            int ixj = t ^ j;
            if (ixj > t) {
                bool desc = ((t & k) == 0);
                float v1 = sv[t], v2 = sv[ixj];
                int   i1 = si[t], i2 = si[ixj];
                bool less = (v1 < v2) || (v1 == v2 && i1 > i2);
                bool sw = desc ? less : !less;
                if (sw) {
                    sv[t] = v2; sv[ixj] = v1;
                    si[t] = i2; si[ixj] = i1;
                }
            }
            __syncthreads();
        }
    }
    const int kmax = g_kmax;
    const int kper = g_kper[b];
    sfl[si[t]] = (t < kmax) ? 1 : 0;
    __syncthreads();
    const int sel   = sfl[t];
    const int tier2 = (int)g_tier2[b*512 + t];
    const int a1 = sel & (tier2 ^ 1);
    const int a2 = sel & tier2;
    sA[t] = a1 | (a2 << 16);
    __syncthreads();
    for (int off = 1; off < 512; off <<= 1) {
        int add = (t >= off) ? sA[t-off] : 0;
        __syncthreads();
        sA[t] += add;
        __syncthreads();
    }
    const int inc1 = sA[t] & 0xffff, inc2 = sA[t] >> 16;
    const int n1   = sA[511] & 0xffff;
    const int excl1 = inc1 - a1, excl2 = inc2 - a2;
    const int kept = (a1 && excl1 < kper) || (a2 && (n1 + excl2) < kper);
    const int nk = 1 - kept;
    __syncthreads();
    sA[t] = kept | (nk << 16);
    __syncthreads();
    for (int off = 1; off < 512; off <<= 1) {
        int add = (t >= off) ? sA[t-off] : 0;
        __syncthreads();
        sA[t] += add;
        __syncthreads();
    }
    const int rk = (sA[t] & 0xffff) - kept;
    const int rn = (sA[t] >> 16) - nk;
    if (kept) g_topk[b*512 + rk] = t;
    else      g_topk[b*512 + kper + rn] = t;
}

// ---------------- gather -> bf16 h_compact ------------------------------------
__global__ __launch_bounds__(64)
void gather_kernel(const float* __restrict__ x)
{
    int row = blockIdx.x;
    int b = row >> 9, j = row & 511;
    int t = threadIdx.x;
    uint2* dst = (uint2*)(g_hcb + (size_t)row * CC);
    if (j < g_kper[b]) {
        int src = g_topk[row];
        float4 v = ((const float4*)(x + ((size_t)b*512 + src) * CC))[t];
        uint2 o; o.x = pk(v.x, v.y); o.y = pk(v.z, v.w);
        dst[t] = o;
    } else {
        dst[t] = make_uint2(0u, 0u);
    }
}

// ---------------- flash attention (fp32 SIMT), bf16 output --------------------
__global__ __launch_bounds__(128)
void attn_kernel()
{
    __shared__ float Ks[16][DHH];
    __shared__ float Vs[16][DHH];
    const int bh = blockIdx.x;
    const int b = bh >> 3, h = bh & 7;
    const int t = threadIdx.x;
    const int q0 = blockIdx.y << 8;
    const int kper = g_kper[b];
    const size_t base = (size_t)b * 512;
    const size_t hoff = (size_t)h * DHH;
    const int qi0 = q0 + t, qi1 = q0 + 128 + t;

    float q[2][DHH], acc[2][DHH];
    {
        const float4* qp0 = (const float4*)(g_qkv + (base + qi0) * 768 + hoff);
        const float4* qp1 = (const float4*)(g_qkv + (base + qi1) * 768 + hoff);
#pragma unroll
        for (int d4 = 0; d4 < 8; d4++) {
            float4 v0 = qp0[d4], v1 = qp1[d4];
            q[0][d4*4+0]=v0.x; q[0][d4*4+1]=v0.y; q[0][d4*4+2]=v0.z; q[0][d4*4+3]=v0.w;
            q[1][d4*4+0]=v1.x; q[1][d4*4+1]=v1.y; q[1][d4*4+2]=v1.z; q[1][d4*4+3]=v1.w;
        }
    }
#pragma unroll
    for (int u = 0; u < 2; u++)
#pragma unroll
        for (int d = 0; d < DHH; d++) acc[u][d] = 0.f;

    float m0 = -1e30f, m1 = -1e30f, l0 = 0.f, l1 = 0.f;
    const float scale = 0.17677669529663687f;
    const int lr  = t >> 3;
    const int lcc = (t & 7) << 2;

    for (int kt = 0; kt < kper; kt += 16) {
        const float* kp = g_qkv + (base + kt + lr) * 768 + 256 + hoff + lcc;
        float4 kv = *(const float4*)kp;
        float4 vv = *(const float4*)(kp + 256);
        __syncthreads();
        *(float4*)&Ks[lr][lcc] = kv;
        *(float4*)&Vs[lr][lcc] = vv;
        __syncthreads();

        const int jmax = min(16, kper - kt);
        float p0[16], p1[16];
        float mt0 = m0, mt1 = m1;
#pragma unroll
        for (int jj = 0; jj < 16; jj++) {
            if (jj < jmax) {
                float s0 = 0.f, s1 = 0.f;
#pragma unroll
                for (int d = 0; d < DHH; d++) {
                    float kd = Ks[jj][d];
                    s0 = fmaf(q[0][d], kd, s0);
                    s1 = fmaf(q[1][d], kd, s1);
                }
                s0 *= scale; s1 *= scale;
                p0[jj] = s0; p1[jj] = s1;
                mt0 = fmaxf(mt0, s0); mt1 = fmaxf(mt1, s1);
            } else { p0[jj] = -1e30f; p1[jj] = -1e30f; }
        }
        float sf0 = __expf(m0 - mt0), sf1 = __expf(m1 - mt1);
        l0 *= sf0; l1 *= sf1;
#pragma unroll
        for (int d = 0; d < DHH; d++) { acc[0][d] *= sf0; acc[1][d] *= sf1; }
        m0 = mt0; m1 = mt1;
#pragma unroll
        for (int jj = 0; jj < 16; jj++) {
            float e0 = __expf(p0[jj] - m0);
            float e1 = __expf(p1[jj] - m1);
            l0 += e0; l1 += e1;
#pragma unroll
            for (int d = 0; d < DHH; d++) {
                float vd = Vs[jj][d];
                acc[0][d] = fmaf(e0, vd, acc[0][d]);
                acc[1][d] = fmaf(e1, vd, acc[1][d]);
            }
        }
    }
    float inv0 = 1.f / l0, inv1 = 1.f / l1;
    uint2* o0 = (uint2*)(g_aob + (base + qi0) * CC + hoff);
    uint2* o1 = (uint2*)(g_aob + (base + qi1) * CC + hoff);
#pragma unroll
    for (int g = 0; g < 8; g++) {
        uint2 p0v, p1v;
        p0v.x = pk(acc[0][g*4+0]*inv0, acc[0][g*4+1]*inv0);
        p0v.y = pk(acc[0][g*4+2]*inv0, acc[0][g*4+3]*inv0);
        p1v.x = pk(acc[1][g*4+0]*inv1, acc[1][g*4+1]*inv1);
        p1v.y = pk(acc[1][g*4+2]*inv1, acc[1][g*4+3]*inv1);
        o0[g] = p0v;
        o1[g] = p1v;
    }
}

// ---------------- h = x * ratio (fp32 + bf16) ---------------------------------
__global__ __launch_bounds__(256)
void hbase_kernel(const float* __restrict__ x, const float* __restrict__ ratio)
{
    int i = blockIdx.x * 256 + threadIdx.x;   // float4 index
    int b = i >> 15;
    float r = ratio[b];
    float4 v = ((const float4*)x)[i];
    float4 o = make_float4(v.x*r, v.y*r, v.z*r, v.w*r);
    ((float4*)g_h)[i] = o;
    uint2 p; p.x = pk(o.x, o.y); p.y = pk(o.z, o.w);
    ((uint2*)g_hb)[i] = p;
}

// ---------------- scatter h_attn back + residual + scale ----------------------
__global__ __launch_bounds__(64)
void scatter_kernel(const float* __restrict__ x, const float* __restrict__ ratio)
{
    int row = blockIdx.x;
    int b = row >> 9, j = row & 511;
    if (j >= g_kmax) return;
    int dst = g_topk[row];
    size_t n = (size_t)b * 512 + dst;
    float r = ratio[b];
    int t = threadIdx.x;
    float4 ha = ((const float4*)(g_hattn + (size_t)row * CC))[t];
    float4 xv = ((const float4*)(x + n * CC))[t];
    float4 o = make_float4((ha.x+xv.x)*r, (ha.y+xv.y)*r, (ha.z+xv.z)*r, (ha.w+xv.w)*r);
    ((float4*)(g_h + n * CC))[t] = o;
    uint2 p; p.x = pk(o.x, o.y); p.y = pk(o.z, o.w);
    ((uint2*)(g_hb + n * CC))[t] = p;
}

// ------------------------------------------------------------------------------
extern "C" void kernel_launch(void* const* d_in, const int* in_sizes, int n_in,
                              void* d_out, int out_size)
{
    (void)in_sizes; (void)n_in; (void)out_size;
    const float* x      = (const float*)d_in[0];
    const float* ratio  = (const float*)d_in[3];
    const float* gumbel = (const float*)d_in[4];
    const float* Ws1    = (const float*)d_in[5];
    const float* bs1    = (const float*)d_in[6];
    const float* Ws2    = (const float*)d_in[7];
    const float* bs2    = (const float*)d_in[8];
    const float* Win    = (const float*)d_in[9];
    const float* b_in   = (const float*)d_in[10];
    const float* Wout   = (const float*)d_in[11];
    const float* bout   = (const float*)d_in[12];
    const float* Wm1    = (const float*)d_in[13];
    const float* bm1    = (const float*)d_in[14];
    const float* Wm2    = (const float*)d_in[15];
    const float* bm2    = (const float*)d_in[16];
    float* out = (float*)d_out;

    float *s1p, *qkvp, *hattnp, *hp;
    __nv_bfloat16 *hcbp, *aobp, *hbp, *midbp, *winbp, *woutbp, *wm1bp, *wm2bp;
    cudaGetSymbolAddress((void**)&s1p,    g_s1);
    cudaGetSymbolAddress((void**)&qkvp,   g_qkv);
    cudaGetSymbolAddress((void**)&hattnp, g_hattn);
    cudaGetSymbolAddress((void**)&hp,     g_h);
    cudaGetSymbolAddress((void**)&hcbp,   g_hcb);
    cudaGetSymbolAddress((void**)&aobp,   g_aob);
    cudaGetSymbolAddress((void**)&hbp,    g_hb);
    cudaGetSymbolAddress((void**)&midbp,  g_midb);
    cudaGetSymbolAddress((void**)&winbp,  g_Winb);
    cudaGetSymbolAddress((void**)&woutbp, g_Woutb);
    cudaGetSymbolAddress((void**)&wm1bp,  g_Wm1b);
    cudaGetSymbolAddress((void**)&wm2bp,  g_Wm2b);

    // weight conversions (independent)
    f2bf_kernel<<<(3*CC*CC)/1024, 256>>>(Win,  winbp);
    f2bf_kernel<<<(CC*CC)/1024,   256>>>(Wout, woutbp);
    f2bf_kernel<<<(2*CC*CC)/1024, 256>>>(Wm1,  wm1bp);
    f2bf_kernel<<<(2*CC*CC)/1024, 256>>>(Wm2,  wm2bp);

    // 1. scorer (fp32, selection-critical)
    gemm_kernel<1,0><<<dim3(CC/128, NTOK/128), 256>>>(x, Ws1, bs1, nullptr, s1p, NTOK, CC, CC);
    score_kernel<<<NTOK/8, 256>>>(Ws2, bs2);
    softmax_kernel<<<BB, 512>>>(gumbel);
    kper_kernel<<<1, 64>>>(ratio);
    topk_kernel<<<BB, 512>>>();
    // 2. gather (bf16)
    gather_kernel<<<NTOK, 64>>>(x);
    // 3. qkv = h_compact @ Win^T + b_in  (HMMA bf16 -> fp32)
    wmma_gemm<0,0,0><<<dim3(6, NTOK/128), 256>>>(hcbp, winbp, b_in, nullptr,
                                                 qkvp, nullptr, NTOK, 3*CC, CC);
    // 4. attention (fp32 SIMT, bf16 out)
    attn_kernel<<<dim3(BB*HH, 2), 128>>>();
    // 5. h_attn = ao @ Wout^T + bout
    wmma_gemm<0,0,0><<<dim3(2, NTOK/128), 256>>>(aobp, woutbp, bout, nullptr,
                                                 hattnp, nullptr, NTOK, CC, CC);
    // 6. h base + scatter (fp32 + bf16 copies)
    hbase_kernel<<<(NTOK*CC/4)/256, 256>>>(x, ratio);
    scatter_kernel<<<NTOK, 64>>>(x, ratio);
    // 7. mid = relu(h @ Wm1^T + bm1)  (bf16 out)
    wmma_gemm<1,0,1><<<dim3(4, NTOK/128), 256>>>(hbp, wm1bp, bm1, nullptr,
                                                 nullptr, midbp, NTOK, 2*CC, CC);
    // 8. out = h + mid @ Wm2^T + bm2
    wmma_gemm<0,1,0><<<dim3(2, NTOK/128), 256>>>(midbp, wm2bp, bm2, hp,
                                                 out, nullptr, NTOK, CC, 2*CC);
}

// round 11
// speedup vs baseline: 3.0583x; 1.5621x over previous
#include <cuda_runtime.h>
#include <cuda_bf16.h>
#include <math.h>
#include <stdint.h>

#define BB   64
#define LL   512
#define CC   256
#define HH   8
#define DHH  32
#define NTOK (BB*LL)

// ---------------- scratch (static __device__, no allocations) ----------------
__device__ float g_s1[(size_t)NTOK*CC];       // scorer hidden (fp32)
__device__ float g_z[BB*LL];                  // raw scores
__device__ float g_sv[BB*LL];                 // y_soft values (jax-replicated)
__device__ unsigned char g_tier2[BB*LL];      // token_mask residue flag
__device__ int   g_kper[BB];
__device__ int   g_kmax;
__device__ int   g_topk[BB*LL];
__device__ float g_hattn[(size_t)NTOK*CC];    // fp32 Wout output
__device__ float g_h[(size_t)NTOK*CC];        // fp32 residual-scaled hidden
// bf16 operands for tensor-core GEMMs / attention
__device__ __nv_bfloat16 g_qkvb[(size_t)NTOK*3*CC];
__device__ __nv_bfloat16 g_hcb [(size_t)NTOK*CC];
__device__ __nv_bfloat16 g_aob [(size_t)NTOK*CC];
__device__ __nv_bfloat16 g_hb  [(size_t)NTOK*CC];
__device__ __nv_bfloat16 g_midb[(size_t)NTOK*2*CC];
__device__ __nv_bfloat16 g_Winb [3*CC*CC];
__device__ __nv_bfloat16 g_Woutb[CC*CC];
__device__ __nv_bfloat16 g_Wm1b [2*CC*CC];
__device__ __nv_bfloat16 g_Wm2b [CC*2*CC];

// ---------------- helpers -----------------------------------------------------
__device__ __forceinline__ uint32_t smem_u32(const void* p){
    uint32_t a;
    asm("{ .reg .u64 t; cvta.to.shared.u64 t, %1; cvt.u32.u64 %0, t; }" : "=r"(a) : "l"(p));
    return a;
}
__device__ __forceinline__ uint32_t pk(float a, float b){
    __nv_bfloat162 t = __floats2bfloat162_rn(a, b);
    return *reinterpret_cast<uint32_t*>(&t);
}
__device__ __forceinline__ void ldsm4(uint32_t& r0, uint32_t& r1, uint32_t& r2, uint32_t& r3,
                                      uint32_t addr){
    asm volatile("ldmatrix.sync.aligned.m8n8.x4.shared.b16 {%0,%1,%2,%3}, [%4];"
                 : "=r"(r0), "=r"(r1), "=r"(r2), "=r"(r3) : "r"(addr));
}
__device__ __forceinline__ void mma_bf16(float* c, const uint32_t* a, const uint32_t* b){
    asm volatile("mma.sync.aligned.m16n8k16.row.col.f32.bf16.bf16.f32 "
                 "{%0,%1,%2,%3}, {%4,%5,%6,%7}, {%8,%9}, {%0,%1,%2,%3};"
                 : "+f"(c[0]), "+f"(c[1]), "+f"(c[2]), "+f"(c[3])
                 : "r"(a[0]), "r"(a[1]), "r"(a[2]), "r"(a[3]), "r"(b[0]), "r"(b[1]));
}

// ---------------- warp-MMA bf16 GEMM: out = act(A@W^T + bias) (+res) ----------
#define SROW 40   // smem row stride in bf16 (padded, 80B)

template<int ACT, int RES, int OUTBF>
__global__ __launch_bounds__(256)
void wmma_gemm(const __nv_bfloat16* __restrict__ A, const __nv_bfloat16* __restrict__ W,
               const float* __restrict__ bias, const float* __restrict__ res,
               float* __restrict__ outf, __nv_bfloat16* __restrict__ outb,
               int M, int N, int K)
{
    __shared__ __align__(16) __nv_bfloat16 As[128*SROW];
    __shared__ __align__(16) __nv_bfloat16 Bs[128*SROW];
    const uint32_t as_b = smem_u32(As);
    const uint32_t bs_b = smem_u32(Bs);
    const int tid  = threadIdx.x;
    const int wid  = tid >> 5, lane = tid & 31;
    const int bm   = blockIdx.y << 7;
    const int bn   = blockIdx.x << 7;
    const int wm   = wid & 3;
    const int wn   = wid >> 2;

    const int lrow0 = (tid >> 2);
    const int lch   = (tid & 3) << 3;
    const __nv_bfloat16* Ap0 = A + (size_t)(bm + lrow0     ) * K + lch;
    const __nv_bfloat16* Ap1 = A + (size_t)(bm + lrow0 + 64) * K + lch;
    const __nv_bfloat16* Wp0 = W + (size_t)(bn + lrow0     ) * K + lch;
    const __nv_bfloat16* Wp1 = W + (size_t)(bn + lrow0 + 64) * K + lch;
    const uint32_t soff0 = (uint32_t)(lrow0      * SROW + lch) * 2;
    const uint32_t soff1 = (uint32_t)((lrow0+64) * SROW + lch) * 2;

    const uint32_t a_row = (uint32_t)(wm*32 + (lane & 15));
    const uint32_t a_kad = (uint32_t)((lane >> 4) << 3);
    const uint32_t b_row = (uint32_t)(wn*64 + ((lane >> 4) << 3) + (lane & 7));
    const uint32_t b_kad = (uint32_t)(((lane >> 3) & 1) << 3);

    float acc[2][8][4];
#pragma unroll
    for (int i = 0; i < 2; i++)
#pragma unroll
        for (int j = 0; j < 8; j++)
#pragma unroll
            for (int q = 0; q < 4; q++) acc[i][j][q] = 0.f;

    uint4 ra0 = *(const uint4*)Ap0, ra1 = *(const uint4*)Ap1;
    uint4 rb0 = *(const uint4*)Wp0, rb1 = *(const uint4*)Wp1;

    for (int k0 = 0; k0 < K; k0 += 32) {
        __syncthreads();
        asm volatile("st.shared.v4.b32 [%0], {%1,%2,%3,%4};"
                     :: "r"(as_b + soff0), "r"(ra0.x), "r"(ra0.y), "r"(ra0.z), "r"(ra0.w) : "memory");
        asm volatile("st.shared.v4.b32 [%0], {%1,%2,%3,%4};"
                     :: "r"(as_b + soff1), "r"(ra1.x), "r"(ra1.y), "r"(ra1.z), "r"(ra1.w) : "memory");
        asm volatile("st.shared.v4.b32 [%0], {%1,%2,%3,%4};"
                     :: "r"(bs_b + soff0), "r"(rb0.x), "r"(rb0.y), "r"(rb0.z), "r"(rb0.w) : "memory");
        asm volatile("st.shared.v4.b32 [%0], {%1,%2,%3,%4};"
                     :: "r"(bs_b + soff1), "r"(rb1.x), "r"(rb1.y), "r"(rb1.z), "r"(rb1.w) : "memory");
        __syncthreads();
        if (k0 + 32 < K) {
            ra0 = *(const uint4*)(Ap0 + k0 + 32); ra1 = *(const uint4*)(Ap1 + k0 + 32);
            rb0 = *(const uint4*)(Wp0 + k0 + 32); rb1 = *(const uint4*)(Wp1 + k0 + 32);
        }
#pragma unroll
        for (int ks = 0; ks < 2; ks++) {
            const uint32_t kcol = (uint32_t)(ks << 4);
            uint32_t a[2][4];
#pragma unroll
            for (int tm = 0; tm < 2; tm++) {
                uint32_t ad = as_b + ((a_row + tm*16) * SROW + kcol + a_kad) * 2;
                ldsm4(a[tm][0], a[tm][1], a[tm][2], a[tm][3], ad);
            }
            uint32_t b[8][2];
#pragma unroll
            for (int tp = 0; tp < 4; tp++) {
                uint32_t bd = bs_b + ((b_row + tp*16) * SROW + kcol + b_kad) * 2;
                ldsm4(b[2*tp][0], b[2*tp][1], b[2*tp+1][0], b[2*tp+1][1], bd);
            }
#pragma unroll
            for (int tm = 0; tm < 2; tm++)
#pragma unroll
                for (int tn = 0; tn < 8; tn++)
                    mma_bf16(acc[tm][tn], a[tm], b[tn]);
        }
    }

#pragma unroll
    for (int tm = 0; tm < 2; tm++) {
        const int gm = bm + wm*32 + tm*16 + (lane >> 2);
#pragma unroll
        for (int tn = 0; tn < 8; tn++) {
            const int gn = bn + wn*64 + tn*8 + ((lane & 3) << 1);
            const float b0 = bias[gn], b1 = bias[gn+1];
#pragma unroll
            for (int half = 0; half < 2; half++) {
                const int m = gm + half*8;
                float v0 = acc[tm][tn][2*half+0] + b0;
                float v1 = acc[tm][tn][2*half+1] + b1;
                if (ACT) { v0 = fmaxf(v0, 0.f); v1 = fmaxf(v1, 0.f); }
                const size_t o = (size_t)m * N + gn;
                if (RES) {
                    float2 r = *(const float2*)(res + o);
                    v0 += r.x; v1 += r.y;
                }
                if (OUTBF) *(uint32_t*)(outb + o) = pk(v0, v1);
                else       *(float2*)(outf + o)   = make_float2(v0, v1);
            }
        }
    }
}

// ---------------- fp32 SIMT GEMM (scorer only — selection-critical) ----------
template<int ACT, int RES>
__global__ __launch_bounds__(256)
void gemm_kernel(const float* __restrict__ A, const float* __restrict__ W,
                 const float* __restrict__ bias, const float* __restrict__ res,
                 float* __restrict__ out, int M, int N, int K)
{
    __shared__ float As[8][132];
    __shared__ float Bs[8][132];
    const int tid = threadIdx.x;
    const int tx = tid & 15, ty = tid >> 4;
    const int bm = blockIdx.y << 7, bn = blockIdx.x << 7;
    const int lr = tid >> 1;
    const int lc = (tid & 1) << 2;

    float acc[8][8];
#pragma unroll
    for (int i = 0; i < 8; i++)
#pragma unroll
        for (int j = 0; j < 8; j++) acc[i][j] = 0.f;

    const float* Ap = A + (size_t)(bm + lr) * K + lc;
    const float* Wp = W + (size_t)(bn + lr) * K + lc;

    for (int k0 = 0; k0 < K; k0 += 8) {
        float4 av = *(const float4*)(Ap + k0);
        float4 wv = *(const float4*)(Wp + k0);
        __syncthreads();
        As[lc+0][lr]=av.x; As[lc+1][lr]=av.y; As[lc+2][lr]=av.z; As[lc+3][lr]=av.w;
        Bs[lc+0][lr]=wv.x; Bs[lc+1][lr]=wv.y; Bs[lc+2][lr]=wv.z; Bs[lc+3][lr]=wv.w;
        __syncthreads();
#pragma unroll
        for (int kk = 0; kk < 8; kk++) {
            float a[8], b[8];
            *(float4*)&a[0] = *(const float4*)&As[kk][ty*8];
            *(float4*)&a[4] = *(const float4*)&As[kk][ty*8+4];
            *(float4*)&b[0] = *(const float4*)&Bs[kk][tx*8];
            *(float4*)&b[4] = *(const float4*)&Bs[kk][tx*8+4];
#pragma unroll
            for (int i = 0; i < 8; i++)
#pragma unroll
                for (int j = 0; j < 8; j++)
                    acc[i][j] = fmaf(a[i], b[j], acc[i][j]);
        }
    }

#pragma unroll
    for (int i = 0; i < 8; i++) {
        const size_t m = (size_t)bm + ty*8 + i;
#pragma unroll
        for (int j4 = 0; j4 < 2; j4++) {
            const int n = bn + tx*8 + j4*4;
            float v[4];
#pragma unroll
            for (int j = 0; j < 4; j++) {
                float t = acc[i][j4*4+j] + bias[n+j];
                if (ACT) t = fmaxf(t, 0.f);
                if (RES) t += res[m*N + n + j];
                v[j] = t;
            }
            *(float4*)(out + m*N + n) = make_float4(v[0],v[1],v[2],v[3]);
        }
    }
}

// ---------------- weight fp32 -> bf16 ----------------------------------------
__global__ __launch_bounds__(256)
void f2bf_kernel(const float* __restrict__ s, __nv_bfloat16* __restrict__ d)
{
    int i = blockIdx.x * 256 + threadIdx.x;
    float4 v = ((const float4*)s)[i];
    uint2 p; p.x = pk(v.x, v.y); p.y = pk(v.z, v.w);
    ((uint2*)d)[i] = p;
}

// ---------------- raw scores: z[n] = s1[n]·Ws2 + bs2 --------------------------
__global__ __launch_bounds__(256)
void score_kernel(const float* __restrict__ Ws2, const float* __restrict__ bs2)
{
    int gid  = blockIdx.x * 256 + threadIdx.x;
    int n    = gid >> 5;
    int lane = gid & 31;
    const float4* r4 = (const float4*)(g_s1 + (size_t)n * CC);
    const float4* w4 = (const float4*)Ws2;
    float4 a0 = r4[lane*2],   b0 = w4[lane*2];
    float4 a1 = r4[lane*2+1], b1 = w4[lane*2+1];
    float s = a0.x*b0.x + a0.y*b0.y + a0.z*b0.z + a0.w*b0.w
            + a1.x*b1.x + a1.y*b1.y + a1.z*b1.z + a1.w*b1.w;
#pragma unroll
    for (int o = 16; o; o >>= 1) s += __shfl_down_sync(0xffffffffu, s, o);
    if (lane == 0) g_z[n] = s + bs2[0];
}

// ---------------- jax-replicated softmax pipeline + tier flag -----------------
__global__ __launch_bounds__(512)
void softmax_kernel(const float* __restrict__ gumbel)
{
    __shared__ float red[512];
    const int b = blockIdx.x, t = threadIdx.x;
    const int n = b * 512 + t;
    float sc = g_z[n];

    red[t] = sc; __syncthreads();
#pragma unroll
    for (int s = 256; s; s >>= 1) { if (t < s) red[t] = fmaxf(red[t], red[t+s]); __syncthreads(); }
    float m1 = red[0]; __syncthreads();

    float sh = __fadd_rn(sc, -m1);
    float e1 = expf(sh);
    red[t] = e1; __syncthreads();
#pragma unroll
    for (int s = 256; s; s >>= 1) { if (t < s) red[t] = __fadd_rn(red[t], red[t+s]); __syncthreads(); }
    float L = logf(red[0]); __syncthreads();

    float ls = __fadd_rn(sh, -L);
    float z  = __fadd_rn(ls, gumbel[n]);
    red[t] = z; __syncthreads();
#pragma unroll
    for (int s = 256; s; s >>= 1) { if (t < s) red[t] = fmaxf(red[t], red[t+s]); __syncthreads(); }
    float m2 = red[0]; __syncthreads();

    float e2 = expf(__fadd_rn(z, -m2));
    red[t] = e2; __syncthreads();
#pragma unroll
    for (int s = 256; s; s >>= 1) { if (t < s) red[t] = __fadd_rn(red[t], red[t+s]); __syncthreads(); }
    float S = red[0];

    float sval = __fdiv_rn(e2, S);
    g_sv[n] = sval;
    float tt = __fadd_rn(__fadd_rn(1.0f, sval), -sval);
    g_tier2[n] = (tt != 1.0f) ? 1 : 0;
}

// ---------------- k_per / k_max ----------------------------------------------
__global__ void kper_kernel(const float* __restrict__ ratio)
{
    __shared__ int sm[64];
    int b = threadIdx.x;
    int kp = (int)ceilf(ratio[b] * 512.0f);
    if (kp < 1)  kp = 1;
    if (kp > LL) kp = LL;
    g_kper[b] = kp;
    sm[b] = kp;
    __syncthreads();
    for (int s = 32; s > 0; s >>= 1) {
        if (b < s) sm[b] = max(sm[b], sm[b+s]);
        __syncthreads();
    }
    if (b == 0) g_kmax = sm[0];
}

// ---------------- per-batch selection (tier-aware, replicates reference) ------
__global__ __launch_bounds__(512)
void topk_kernel()
{
    __shared__ float sv[512];
    __shared__ int   si[512];
    __shared__ int   sfl[512];
    __shared__ int   sA[512];
    const int b = blockIdx.x, t = threadIdx.x;
    sv[t] = g_sv[b*512 + t];
    si[t] = t;
    __syncthreads();
    for (int k = 2; k <= 512; k <<= 1) {
        for (int j = k >> 1; j > 0; j >>= 1) {
            int ixj = t ^ j;
            if (ixj > t) {
                bool desc = ((t & k) == 0);
                float v1 = sv[t], v2 = sv[ixj];
                int   i1 = si[t], i2 = si[ixj];
                bool less = (v1 < v2) || (v1 == v2 && i1 > i2);
                bool sw = desc ? less : !less;
                if (sw) {
                    sv[t] = v2; sv[ixj] = v1;
                    si[t] = i2; si[ixj] = i1;
                }
            }
            __syncthreads();
        }
    }
    const int kmax = g_kmax;
    const int kper = g_kper[b];
    sfl[si[t]] = (t < kmax) ? 1 : 0;
    __syncthreads();
    const int sel   = sfl[t];
    const int tier2 = (int)g_tier2[b*512 + t];
    const int a1 = sel & (tier2 ^ 1);
    const int a2 = sel & tier2;
    sA[t] = a1 | (a2 << 16);
    __syncthreads();
    for (int off = 1; off < 512; off <<= 1) {
        int add = (t >= off) ? sA[t-off] : 0;
        __syncthreads();
        sA[t] += add;
        __syncthreads();
    }
    const int inc1 = sA[t] & 0xffff, inc2 = sA[t] >> 16;
    const int n1   = sA[511] & 0xffff;
    const int excl1 = inc1 - a1, excl2 = inc2 - a2;
    const int kept = (a1 && excl1 < kper) || (a2 && (n1 + excl2) < kper);
    const int nk = 1 - kept;
    __syncthreads();
    sA[t] = kept | (nk << 16);
    __syncthreads();
    for (int off = 1; off < 512; off <<= 1) {
        int add = (t >= off) ? sA[t-off] : 0;
        __syncthreads();
        sA[t] += add;
        __syncthreads();
    }
    const int rk = (sA[t] & 0xffff) - kept;
    const int rn = (sA[t] >> 16) - nk;
    if (kept) g_topk[b*512 + rk] = t;
    else      g_topk[b*512 + kper + rn] = t;
}

// ---------------- gather -> bf16 h_compact ------------------------------------
__global__ __launch_bounds__(64)
void gather_kernel(const float* __restrict__ x)
{
    int row = blockIdx.x;
    int b = row >> 9, j = row & 511;
    int t = threadIdx.x;
    uint2* dst = (uint2*)(g_hcb + (size_t)row * CC);
    if (j < g_kper[b]) {
        int src = g_topk[row];
        float4 v = ((const float4*)(x + ((size_t)b*512 + src) * CC))[t];
        uint2 o; o.x = pk(v.x, v.y); o.y = pk(v.z, v.w);
        dst[t] = o;
    } else {
        dst[t] = make_uint2(0u, 0u);
    }
}

// ---------------- flash attention v2 on HMMA (bf16 in, fp32 accum) ------------
// grid: x = b*8+h (512), y = qtile (8 x 64 queries). block 128 (4 warps x 16q).
#define QS 40   // Q/K smem stride (bf16)
#define VS 72   // Vt smem stride (bf16)
__global__ __launch_bounds__(128)
void attn_mma_kernel()
{
    __shared__ __align__(16) __nv_bfloat16 Qs[64*QS];
    __shared__ __align__(16) __nv_bfloat16 Ks[64*QS];
    __shared__ __align__(16) __nv_bfloat16 Vt[32*VS];
    const uint32_t qs_b = smem_u32(Qs);
    const uint32_t ks_b = smem_u32(Ks);
    const uint32_t vt_b = smem_u32(Vt);

    const int bh = blockIdx.x;
    const int b = bh >> 3, h = bh & 7;
    const int q0 = blockIdx.y << 6;
    const int tid = threadIdx.x;
    const int wid = tid >> 5, lane = tid & 31;
    const int kper = g_kper[b];
    const size_t base = (size_t)b * 512;
    const int hq = h * 32;

    // load Q tile [64 x 32]: 256 uint4 loads, 2 per thread (FIXED: full 32 cols)
#pragma unroll
    for (int i = 0; i < 2; i++) {
        int idx = tid + i*128;
        int row = idx >> 2, qt = idx & 3;
        const uint4 v = *(const uint4*)(g_qkvb + (base + q0 + row) * 768 + hq + qt*8);
        *(uint4*)((char*)Qs + (row*QS + qt*8)*2) = v;
    }

    // A fragments for Q (held in regs across all chunks)
    const uint32_t a_row = (uint32_t)(wid*16 + (lane & 15));
    const uint32_t a_kad = (uint32_t)((lane >> 4) << 3);
    const uint32_t b_rw  = (uint32_t)(((lane >> 4) << 3) + (lane & 7));
    const uint32_t b_kad = (uint32_t)(((lane >> 3) & 1) << 3);
    __syncthreads();
    uint32_t aq[2][4];
#pragma unroll
    for (int ks = 0; ks < 2; ks++)
        ldsm4(aq[ks][0], aq[ks][1], aq[ks][2], aq[ks][3],
              qs_b + (a_row*QS + ks*16 + a_kad)*2);

    float co[4][4];
#pragma unroll
    for (int i = 0; i < 4; i++)
#pragma unroll
        for (int j = 0; j < 4; j++) co[i][j] = 0.f;
    float m0 = -1e30f, m1 = -1e30f, l0 = 0.f, l1 = 0.f;
    const float scale = 0.17677669529663687f;  // 1/sqrt(32)
    const int colb = (lane & 3) << 1;

    for (int kt = 0; kt < kper; kt += 64) {
        __syncthreads();
        // load K chunk [64 x 32]: 2 uint4 per thread (FIXED: full 32 cols)
#pragma unroll
        for (int i = 0; i < 2; i++) {
            int idx = tid + i*128;
            int row = idx >> 2, qt = idx & 3;
            int rk = min(kt + row, 511);
            const uint4 v = *(const uint4*)(g_qkvb + (base + rk) * 768 + 256 + hq + qt*8);
            *(uint4*)((char*)Ks + (row*QS + qt*8)*2) = v;
        }
        // load V chunk transposed -> Vt[dim][key]
#pragma unroll
        for (int i = 0; i < 4; i++) {
            int idx = tid + i*128;
            int key = idx >> 3, dg = (idx & 7) << 2;
            int rk = min(kt + key, 511);
            const uint2 v = *(const uint2*)(g_qkvb + (base + rk) * 768 + 512 + hq + dg);
            const __nv_bfloat16* pv = (const __nv_bfloat16*)&v;
            Vt[(dg+0)*VS + key] = pv[0];
            Vt[(dg+1)*VS + key] = pv[1];
            Vt[(dg+2)*VS + key] = pv[2];
            Vt[(dg+3)*VS + key] = pv[3];
        }
        __syncthreads();

        // S = Q @ K^T  (8 n-tiles of 8 keys)
        float cs[8][4];
#pragma unroll
        for (int nt = 0; nt < 8; nt++)
#pragma unroll
            for (int e = 0; e < 4; e++) cs[nt][e] = 0.f;
#pragma unroll
        for (int ks = 0; ks < 2; ks++) {
            uint32_t bk[8][2];
#pragma unroll
            for (int tp = 0; tp < 4; tp++) {
                uint32_t bd = ks_b + ((tp*16 + b_rw)*QS + ks*16 + b_kad)*2;
                ldsm4(bk[2*tp][0], bk[2*tp][1], bk[2*tp+1][0], bk[2*tp+1][1], bd);
            }
#pragma unroll
            for (int nt = 0; nt < 8; nt++)
                mma_bf16(cs[nt], aq[ks], bk[nt]);
        }
        // scale + mask
#pragma unroll
        for (int nt = 0; nt < 8; nt++) {
            int k0e = kt + nt*8 + colb;
#pragma unroll
            for (int e = 0; e < 4; e++) {
                float s = cs[nt][e] * scale;
                cs[nt][e] = (k0e + (e & 1) < kper) ? s : -1e30f;
            }
        }
        // online softmax (rows g = lane>>2 and g+8)
        float mx0 = -1e30f, mx1 = -1e30f;
#pragma unroll
        for (int nt = 0; nt < 8; nt++) {
            mx0 = fmaxf(mx0, fmaxf(cs[nt][0], cs[nt][1]));
            mx1 = fmaxf(mx1, fmaxf(cs[nt][2], cs[nt][3]));
        }
        mx0 = fmaxf(mx0, __shfl_xor_sync(0xffffffffu, mx0, 1));
        mx0 = fmaxf(mx0, __shfl_xor_sync(0xffffffffu, mx0, 2));
        mx1 = fmaxf(mx1, __shfl_xor_sync(0xffffffffu, mx1, 1));
        mx1 = fmaxf(mx1, __shfl_xor_sync(0xffffffffu, mx1, 2));
        float mn0 = fmaxf(m0, mx0), mn1 = fmaxf(m1, mx1);
        float sf0 = __expf(m0 - mn0), sf1 = __expf(m1 - mn1);
        m0 = mn0; m1 = mn1;
        l0 *= sf0; l1 *= sf1;
#pragma unroll
        for (int nt = 0; nt < 4; nt++) {
            co[nt][0] *= sf0; co[nt][1] *= sf0;
            co[nt][2] *= sf1; co[nt][3] *= sf1;
        }
        // p = exp(s - m), accumulate l, pack to A fragments
        uint32_t pa[4][4];
#pragma unroll
        for (int nt = 0; nt < 8; nt++) {
            float p0 = __expf(cs[nt][0] - m0);
            float p1 = __expf(cs[nt][1] - m0);
            float p2 = __expf(cs[nt][2] - m1);
            float p3 = __expf(cs[nt][3] - m1);
            l0 += p0 + p1; l1 += p2 + p3;
            int kc = nt >> 1, hi = (nt & 1) << 1;
            pa[kc][hi+0] = pk(p0, p1);
            pa[kc][hi+1] = pk(p2, p3);
        }
        // out += P @ V  (4 n-tiles of 8 dims)
#pragma unroll
        for (int kc = 0; kc < 4; kc++) {
            uint32_t bv[4][2];
#pragma unroll
            for (int np = 0; np < 2; np++) {
                uint32_t vd = vt_b + ((np*16 + b_rw)*VS + kc*16 + b_kad)*2;
                ldsm4(bv[2*np][0], bv[2*np][1], bv[2*np+1][0], bv[2*np+1][1], vd);
            }
#pragma unroll
            for (int nt = 0; nt < 4; nt++)
                mma_bf16(co[nt], pa[kc], bv[nt]);
        }
    }
    // final row sums + write bf16
    l0 += __shfl_xor_sync(0xffffffffu, l0, 1);
    l0 += __shfl_xor_sync(0xffffffffu, l0, 2);
    l1 += __shfl_xor_sync(0xffffffffu, l1, 1);
    l1 += __shfl_xor_sync(0xffffffffu, l1, 2);
    float inv0 = 1.f / l0, inv1 = 1.f / l1;
    const int r0 = q0 + wid*16 + (lane >> 2);
#pragma unroll
    for (int nt = 0; nt < 4; nt++) {
        const int col = hq + nt*8 + colb;
        *(uint32_t*)(g_aob + (base + r0    ) * CC + col) = pk(co[nt][0]*inv0, co[nt][1]*inv0);
        *(uint32_t*)(g_aob + (base + r0 + 8) * CC + col) = pk(co[nt][2]*inv1, co[nt][3]*inv1);
    }
}

// ---------------- h = x * ratio (fp32 + bf16) ---------------------------------
__global__ __launch_bounds__(256)
void hbase_kernel(const float* __restrict__ x, const float* __restrict__ ratio)
{
    int i = blockIdx.x * 256 + threadIdx.x;   // float4 index
    int b = i >> 15;
    float r = ratio[b];
    float4 v = ((const float4*)x)[i];
    float4 o = make_float4(v.x*r, v.y*r, v.z*r, v.w*r);
    ((float4*)g_h)[i] = o;
    uint2 p; p.x = pk(o.x, o.y); p.y = pk(o.z, o.w);
    ((uint2*)g_hb)[i] = p;
}

// ---------------- scatter h_attn back + residual + scale ----------------------
__global__ __launch_bounds__(64)
void scatter_kernel(const float* __restrict__ x, const float* __restrict__ ratio)
{
    int row = blockIdx.x;
    int b = row >> 9, j = row & 511;
    if (j >= g_kmax) return;
    int dst = g_topk[row];
    size_t n = (size_t)b * 512 + dst;
    float r = ratio[b];
    int t = threadIdx.x;
    float4 ha = ((const float4*)(g_hattn + (size_t)row * CC))[t];
    float4 xv = ((const float4*)(x + n * CC))[t];
    float4 o = make_float4((ha.x+xv.x)*r, (ha.y+xv.y)*r, (ha.z+xv.z)*r, (ha.w+xv.w)*r);
    ((float4*)(g_h + n * CC))[t] = o;
    uint2 p; p.x = pk(o.x, o.y); p.y = pk(o.z, o.w);
    ((uint2*)(g_hb + n * CC))[t] = p;
}

// ------------------------------------------------------------------------------
extern "C" void kernel_launch(void* const* d_in, const int* in_sizes, int n_in,
                              void* d_out, int out_size)
{
    (void)in_sizes; (void)n_in; (void)out_size;
    const float* x      = (const float*)d_in[0];
    const float* ratio  = (const float*)d_in[3];
    const float* gumbel = (const float*)d_in[4];
    const float* Ws1    = (const float*)d_in[5];
    const float* bs1    = (const float*)d_in[6];
    const float* Ws2    = (const float*)d_in[7];
    const float* bs2    = (const float*)d_in[8];
    const float* Win    = (const float*)d_in[9];
    const float* b_in   = (const float*)d_in[10];
    const float* Wout   = (const float*)d_in[11];
    const float* bout   = (const float*)d_in[12];
    const float* Wm1    = (const float*)d_in[13];
    const float* bm1    = (const float*)d_in[14];
    const float* Wm2    = (const float*)d_in[15];
    const float* bm2    = (const float*)d_in[16];
    float* out = (float*)d_out;

    float *s1p, *hattnp, *hp;
    __nv_bfloat16 *qkvbp, *hcbp, *aobp, *hbp, *midbp, *winbp, *woutbp, *wm1bp, *wm2bp;
    cudaGetSymbolAddress((void**)&s1p,    g_s1);
    cudaGetSymbolAddress((void**)&hattnp, g_hattn);
    cudaGetSymbolAddress((void**)&hp,     g_h);
    cudaGetSymbolAddress((void**)&qkvbp,  g_qkvb);
    cudaGetSymbolAddress((void**)&hcbp,   g_hcb);
    cudaGetSymbolAddress((void**)&aobp,   g_aob);
    cudaGetSymbolAddress((void**)&hbp,    g_hb);
    cudaGetSymbolAddress((void**)&midbp,  g_midb);
    cudaGetSymbolAddress((void**)&winbp,  g_Winb);
    cudaGetSymbolAddress((void**)&woutbp, g_Woutb);
    cudaGetSymbolAddress((void**)&wm1bp,  g_Wm1b);
    cudaGetSymbolAddress((void**)&wm2bp,  g_Wm2b);

    // weight conversions (independent)
    f2bf_kernel<<<(3*CC*CC)/1024, 256>>>(Win,  winbp);
    f2bf_kernel<<<(CC*CC)/1024,   256>>>(Wout, woutbp);
    f2bf_kernel<<<(2*CC*CC)/1024, 256>>>(Wm1,  wm1bp);
    f2bf_kernel<<<(2*CC*CC)/1024, 256>>>(Wm2,  wm2bp);

    // 1. scorer (fp32, selection-critical — bit-faithful, do not touch)
    gemm_kernel<1,0><<<dim3(CC/128, NTOK/128), 256>>>(x, Ws1, bs1, nullptr, s1p, NTOK, CC, CC);
    score_kernel<<<NTOK/8, 256>>>(Ws2, bs2);
    softmax_kernel<<<BB, 512>>>(gumbel);
    kper_kernel<<<1, 64>>>(ratio);
    topk_kernel<<<BB, 512>>>();
    // 2. gather (bf16)
    gather_kernel<<<NTOK, 64>>>(x);
    // 3. qkv = h_compact @ Win^T + b_in  (HMMA, bf16 out)
    wmma_gemm<0,0,1><<<dim3(6, NTOK/128), 256>>>(hcbp, winbp, b_in, nullptr,
                                                 nullptr, qkvbp, NTOK, 3*CC, CC);
    // 4. attention (HMMA flash-attn, bf16 out)
    attn_mma_kernel<<<dim3(BB*HH, 8), 128>>>();
    // 5. h_attn = ao @ Wout^T + bout
    wmma_gemm<0,0,0><<<dim3(2, NTOK/128), 256>>>(aobp, woutbp, bout, nullptr,
                                                 hattnp, nullptr, NTOK, CC, CC);
    // 6. h base + scatter (fp32 + bf16 copies)
    hbase_kernel<<<(NTOK*CC/4)/256, 256>>>(x, ratio);
    scatter_kernel<<<NTOK, 64>>>(x, ratio);
    // 7. mid = relu(h @ Wm1^T + bm1)  (bf16 out)
    wmma_gemm<1,0,1><<<dim3(4, NTOK/128), 256>>>(hbp, wm1bp, bm1, nullptr,
                                                 nullptr, midbp, NTOK, 2*CC, CC);
    // 8. out = h + mid @ Wm2^T + bm2
    wmma_gemm<0,1,0><<<dim3(2, NTOK/128), 256>>>(midbp, wm2bp, bm2, hp,
                                                 out, nullptr, NTOK, CC, 2*CC);
}

// round 13
// speedup vs baseline: 3.2472x; 1.0618x over previous
#include <cuda_runtime.h>
#include <cuda_bf16.h>
#include <math.h>
#include <stdint.h>

#define BB   64
#define LL   512
#define CC   256
#define HH   8
#define DHH  32
#define NTOK (BB*LL)

// ---------------- scratch (static __device__, no allocations) ----------------
__device__ float g_s1[(size_t)NTOK*CC];       // scorer hidden (fp32)
__device__ float g_z[BB*LL];                  // raw scores
__device__ float g_sv[BB*LL];                 // y_soft values (jax-replicated)
__device__ unsigned char g_tier2[BB*LL];      // token_mask residue flag
__device__ int   g_kper[BB];
__device__ int   g_kmax;
__device__ int   g_topk[BB*LL];
__device__ float g_h[(size_t)NTOK*CC];        // fp32 residual-scaled hidden
// bf16 operands for tensor-core GEMMs / attention
__device__ __nv_bfloat16 g_qkvb[(size_t)NTOK*3*CC];
__device__ __nv_bfloat16 g_hcb [(size_t)NTOK*CC];
__device__ __nv_bfloat16 g_aob [(size_t)NTOK*CC];
__device__ __nv_bfloat16 g_hb  [(size_t)NTOK*CC];
__device__ __nv_bfloat16 g_midb[(size_t)NTOK*2*CC];
__device__ __nv_bfloat16 g_Winb [3*CC*CC];
__device__ __nv_bfloat16 g_Woutb[CC*CC];
__device__ __nv_bfloat16 g_Wm1b [2*CC*CC];
__device__ __nv_bfloat16 g_Wm2b [CC*2*CC];

// ---------------- helpers -----------------------------------------------------
__device__ __forceinline__ uint32_t smem_u32(const void* p){
    uint32_t a;
    asm("{ .reg .u64 t; cvta.to.shared.u64 t, %1; cvt.u32.u64 %0, t; }" : "=r"(a) : "l"(p));
    return a;
}
__device__ __forceinline__ uint32_t pk(float a, float b){
    __nv_bfloat162 t = __floats2bfloat162_rn(a, b);
    return *reinterpret_cast<uint32_t*>(&t);
}
__device__ __forceinline__ void ldsm4(uint32_t& r0, uint32_t& r1, uint32_t& r2, uint32_t& r3,
                                      uint32_t addr){
    asm volatile("ldmatrix.sync.aligned.m8n8.x4.shared.b16 {%0,%1,%2,%3}, [%4];"
                 : "=r"(r0), "=r"(r1), "=r"(r2), "=r"(r3) : "r"(addr));
}
__device__ __forceinline__ void mma_bf16(float* c, const uint32_t* a, const uint32_t* b){
    asm volatile("mma.sync.aligned.m16n8k16.row.col.f32.bf16.bf16.f32 "
                 "{%0,%1,%2,%3}, {%4,%5,%6,%7}, {%8,%9}, {%0,%1,%2,%3};"
                 : "+f"(c[0]), "+f"(c[1]), "+f"(c[2]), "+f"(c[3])
                 : "r"(a[0]), "r"(a[1]), "r"(a[2]), "r"(a[3]), "r"(b[0]), "r"(b[1]));
}
__device__ __forceinline__ void cp16(uint32_t dst, const void* src){
    asm volatile("cp.async.cg.shared.global [%0], [%1], 16;" :: "r"(dst), "l"(src) : "memory");
}
#define CP_COMMIT() asm volatile("cp.async.commit_group;" ::: "memory")
#define CP_WAIT0()  asm volatile("cp.async.wait_group 0;"  ::: "memory")

// ---------------- warp-MMA bf16 GEMM: out = act(A@W^T + bias) (+res/+scatter) -
#define SROW 40                      // smem row stride in bf16 (padded, 80B)
#define STAGEB (128*SROW*2)          // stage size in bytes (10240)

template<int ACT, int RES, int OUTBF, int SCAT>
__global__ __launch_bounds__(256)
void wmma_gemm(const __nv_bfloat16* __restrict__ A, const __nv_bfloat16* __restrict__ W,
               const float* __restrict__ bias, const float* __restrict__ res,
               float* __restrict__ outf, __nv_bfloat16* __restrict__ outb,
               const float* __restrict__ ratio,
               int M, int N, int K)
{
    __shared__ __align__(16) __nv_bfloat16 As[2*128*SROW];
    __shared__ __align__(16) __nv_bfloat16 Bs[2*128*SROW];
    const uint32_t as_b = smem_u32(As);
    const uint32_t bs_b = smem_u32(Bs);
    const int tid  = threadIdx.x;
    const int wid  = tid >> 5, lane = tid & 31;
    const int bm   = blockIdx.y << 7;
    const int bn   = blockIdx.x << 7;
    const int wm   = wid & 3;
    const int wn   = wid >> 2;

    const int lrow0 = (tid >> 2);          // 0..63
    const int lch   = (tid & 3) << 3;      // k offset 0,8,16,24
    const __nv_bfloat16* Ap0 = A + (size_t)(bm + lrow0     ) * K + lch;
    const __nv_bfloat16* Ap1 = A + (size_t)(bm + lrow0 + 64) * K + lch;
    const __nv_bfloat16* Wp0 = W + (size_t)(bn + lrow0     ) * K + lch;
    const __nv_bfloat16* Wp1 = W + (size_t)(bn + lrow0 + 64) * K + lch;
    const uint32_t soff0 = (uint32_t)(lrow0      * SROW + lch) * 2;
    const uint32_t soff1 = (uint32_t)((lrow0+64) * SROW + lch) * 2;

    const uint32_t a_row = (uint32_t)(wm*32 + (lane & 15));
    const uint32_t a_kad = (uint32_t)((lane >> 4) << 3);
    const uint32_t b_row = (uint32_t)(wn*64 + ((lane >> 4) << 3) + (lane & 7));
    const uint32_t b_kad = (uint32_t)(((lane >> 3) & 1) << 3);

    float acc[2][8][4];
#pragma unroll
    for (int i = 0; i < 2; i++)
#pragma unroll
        for (int j = 0; j < 8; j++)
#pragma unroll
            for (int q = 0; q < 4; q++) acc[i][j][q] = 0.f;

    const int nc = K >> 5;
    // prologue: stage 0
    {
        cp16(as_b + soff0, Ap0); cp16(as_b + soff1, Ap1);
        cp16(bs_b + soff0, Wp0); cp16(bs_b + soff1, Wp1);
        CP_COMMIT();
    }

    for (int c = 0; c < nc; c++) {
        CP_WAIT0();
        __syncthreads();
        if (c + 1 < nc) {
            const int k1 = (c + 1) << 5;
            const uint32_t sb = ((c + 1) & 1) * STAGEB;
            cp16(as_b + sb + soff0, Ap0 + k1); cp16(as_b + sb + soff1, Ap1 + k1);
            cp16(bs_b + sb + soff0, Wp0 + k1); cp16(bs_b + sb + soff1, Wp1 + k1);
            CP_COMMIT();
        }
        const uint32_t ab = as_b + (c & 1) * STAGEB;
        const uint32_t bb = bs_b + (c & 1) * STAGEB;
#pragma unroll
        for (int ks = 0; ks < 2; ks++) {
            const uint32_t kcol = (uint32_t)(ks << 4);
            uint32_t a[2][4];
#pragma unroll
            for (int tm = 0; tm < 2; tm++) {
                uint32_t ad = ab + ((a_row + tm*16) * SROW + kcol + a_kad) * 2;
                ldsm4(a[tm][0], a[tm][1], a[tm][2], a[tm][3], ad);
            }
            uint32_t b[8][2];
#pragma unroll
            for (int tp = 0; tp < 4; tp++) {
                uint32_t bd = bb + ((b_row + tp*16) * SROW + kcol + b_kad) * 2;
                ldsm4(b[2*tp][0], b[2*tp][1], b[2*tp+1][0], b[2*tp+1][1], bd);
            }
#pragma unroll
            for (int tm = 0; tm < 2; tm++)
#pragma unroll
                for (int tn = 0; tn < 8; tn++)
                    mma_bf16(acc[tm][tn], a[tm], b[tn]);
        }
        __syncthreads();
    }

    if (SCAT) {
        // fused scatter epilogue: h[node] = (acc + bias + x[node]) * ratio[b]
        const int kmax = g_kmax;
#pragma unroll
        for (int tm = 0; tm < 2; tm++) {
#pragma unroll
            for (int half = 0; half < 2; half++) {
                const int m = bm + wm*32 + tm*16 + (lane >> 2) + half*8;
                const int b = m >> 9, j = m & 511;
                if (j >= kmax) continue;
                const int dst = g_topk[m];
                const size_t node = (((size_t)b << 9) + dst) * CC;
                const float r = ratio[b];
#pragma unroll
                for (int tn = 0; tn < 8; tn++) {
                    const int gn = bn + wn*64 + tn*8 + ((lane & 3) << 1);
                    float v0 = acc[tm][tn][2*half+0] + bias[gn];
                    float v1 = acc[tm][tn][2*half+1] + bias[gn+1];
                    float2 xv = *(const float2*)(res + node + gn);
                    v0 = (v0 + xv.x) * r;
                    v1 = (v1 + xv.y) * r;
                    *(float2*)(g_h + node + gn) = make_float2(v0, v1);
                    *(uint32_t*)(g_hb + node + gn) = pk(v0, v1);
                }
            }
        }
        return;
    }

#pragma unroll
    for (int tm = 0; tm < 2; tm++) {
        const int gm = bm + wm*32 + tm*16 + (lane >> 2);
#pragma unroll
        for (int tn = 0; tn < 8; tn++) {
            const int gn = bn + wn*64 + tn*8 + ((lane & 3) << 1);
            const float b0 = bias[gn], b1 = bias[gn+1];
#pragma unroll
            for (int half = 0; half < 2; half++) {
                const int m = gm + half*8;
                float v0 = acc[tm][tn][2*half+0] + b0;
                float v1 = acc[tm][tn][2*half+1] + b1;
                if (ACT) { v0 = fmaxf(v0, 0.f); v1 = fmaxf(v1, 0.f); }
                const size_t o = (size_t)m * N + gn;
                if (RES) {
                    float2 r = *(const float2*)(res + o);
                    v0 += r.x; v1 += r.y;
                }
                if (OUTBF) *(uint32_t*)(outb + o) = pk(v0, v1);
                else       *(float2*)(outf + o)   = make_float2(v0, v1);
            }
        }
    }
}

// ---------------- fp32 SIMT GEMM (scorer only — selection-critical) ----------
template<int ACT, int RES>
__global__ __launch_bounds__(256)
void gemm_kernel(const float* __restrict__ A, const float* __restrict__ W,
                 const float* __restrict__ bias, const float* __restrict__ res,
                 float* __restrict__ out, int M, int N, int K)
{
    __shared__ float As[8][132];
    __shared__ float Bs[8][132];
    const int tid = threadIdx.x;
    const int tx = tid & 15, ty = tid >> 4;
    const int bm = blockIdx.y << 7, bn = blockIdx.x << 7;
    const int lr = tid >> 1;
    const int lc = (tid & 1) << 2;

    float acc[8][8];
#pragma unroll
    for (int i = 0; i < 8; i++)
#pragma unroll
        for (int j = 0; j < 8; j++) acc[i][j] = 0.f;

    const float* Ap = A + (size_t)(bm + lr) * K + lc;
    const float* Wp = W + (size_t)(bn + lr) * K + lc;

    for (int k0 = 0; k0 < K; k0 += 8) {
        float4 av = *(const float4*)(Ap + k0);
        float4 wv = *(const float4*)(Wp + k0);
        __syncthreads();
        As[lc+0][lr]=av.x; As[lc+1][lr]=av.y; As[lc+2][lr]=av.z; As[lc+3][lr]=av.w;
        Bs[lc+0][lr]=wv.x; Bs[lc+1][lr]=wv.y; Bs[lc+2][lr]=wv.z; Bs[lc+3][lr]=wv.w;
        __syncthreads();
#pragma unroll
        for (int kk = 0; kk < 8; kk++) {
            float a[8], b[8];
            *(float4*)&a[0] = *(const float4*)&As[kk][ty*8];
            *(float4*)&a[4] = *(const float4*)&As[kk][ty*8+4];
            *(float4*)&b[0] = *(const float4*)&Bs[kk][tx*8];
            *(float4*)&b[4] = *(const float4*)&Bs[kk][tx*8+4];
#pragma unroll
            for (int i = 0; i < 8; i++)
#pragma unroll
                for (int j = 0; j < 8; j++)
                    acc[i][j] = fmaf(a[i], b[j], acc[i][j]);
        }
    }

#pragma unroll
    for (int i = 0; i < 8; i++) {
        const size_t m = (size_t)bm + ty*8 + i;
#pragma unroll
        for (int j4 = 0; j4 < 2; j4++) {
            const int n = bn + tx*8 + j4*4;
            float v[4];
#pragma unroll
            for (int j = 0; j < 4; j++) {
                float t = acc[i][j4*4+j] + bias[n+j];
                if (ACT) t = fmaxf(t, 0.f);
                if (RES) t += res[m*N + n + j];
                v[j] = t;
            }
            *(float4*)(out + m*N + n) = make_float4(v[0],v[1],v[2],v[3]);
        }
    }
}

// ---------------- weight fp32 -> bf16 ----------------------------------------
__global__ __launch_bounds__(256)
void f2bf_kernel(const float* __restrict__ s, __nv_bfloat16* __restrict__ d)
{
    int i = blockIdx.x * 256 + threadIdx.x;
    float4 v = ((const float4*)s)[i];
    uint2 p; p.x = pk(v.x, v.y); p.y = pk(v.z, v.w);
    ((uint2*)d)[i] = p;
}

// ---------------- raw scores: z[n] = s1[n]·Ws2 + bs2 --------------------------
__global__ __launch_bounds__(256)
void score_kernel(const float* __restrict__ Ws2, const float* __restrict__ bs2)
{
    int gid  = blockIdx.x * 256 + threadIdx.x;
    int n    = gid >> 5;
    int lane = gid & 31;
    const float4* r4 = (const float4*)(g_s1 + (size_t)n * CC);
    const float4* w4 = (const float4*)Ws2;
    float4 a0 = r4[lane*2],   b0 = w4[lane*2];
    float4 a1 = r4[lane*2+1], b1 = w4[lane*2+1];
    float s = a0.x*b0.x + a0.y*b0.y + a0.z*b0.z + a0.w*b0.w
            + a1.x*b1.x + a1.y*b1.y + a1.z*b1.z + a1.w*b1.w;
#pragma unroll
    for (int o = 16; o; o >>= 1) s += __shfl_down_sync(0xffffffffu, s, o);
    if (lane == 0) g_z[n] = s + bs2[0];
}

// ---------------- jax-replicated softmax pipeline + tier flag -----------------
__global__ __launch_bounds__(512)
void softmax_kernel(const float* __restrict__ gumbel)
{
    __shared__ float red[512];
    const int b = blockIdx.x, t = threadIdx.x;
    const int n = b * 512 + t;
    float sc = g_z[n];

    red[t] = sc; __syncthreads();
#pragma unroll
    for (int s = 256; s; s >>= 1) { if (t < s) red[t] = fmaxf(red[t], red[t+s]); __syncthreads(); }
    float m1 = red[0]; __syncthreads();

    float sh = __fadd_rn(sc, -m1);
    float e1 = expf(sh);
    red[t] = e1; __syncthreads();
#pragma unroll
    for (int s = 256; s; s >>= 1) { if (t < s) red[t] = __fadd_rn(red[t], red[t+s]); __syncthreads(); }
    float L = logf(red[0]); __syncthreads();

    float ls = __fadd_rn(sh, -L);
    float z  = __fadd_rn(ls, gumbel[n]);
    red[t] = z; __syncthreads();
#pragma unroll
    for (int s = 256; s; s >>= 1) { if (t < s) red[t] = fmaxf(red[t], red[t+s]); __syncthreads(); }
    float m2 = red[0]; __syncthreads();

    float e2 = expf(__fadd_rn(z, -m2));
    red[t] = e2; __syncthreads();
#pragma unroll
    for (int s = 256; s; s >>= 1) { if (t < s) red[t] = __fadd_rn(red[t], red[t+s]); __syncthreads(); }
    float S = red[0];

    float sval = __fdiv_rn(e2, S);
    g_sv[n] = sval;
    float tt = __fadd_rn(__fadd_rn(1.0f, sval), -sval);
    g_tier2[n] = (tt != 1.0f) ? 1 : 0;
}

// ---------------- k_per / k_max ----------------------------------------------
__global__ void kper_kernel(const float* __restrict__ ratio)
{
    __shared__ int sm[64];
    int b = threadIdx.x;
    int kp = (int)ceilf(ratio[b] * 512.0f);
    if (kp < 1)  kp = 1;
    if (kp > LL) kp = LL;
    g_kper[b] = kp;
    sm[b] = kp;
    __syncthreads();
    for (int s = 32; s > 0; s >>= 1) {
        if (b < s) sm[b] = max(sm[b], sm[b+s]);
        __syncthreads();
    }
    if (b == 0) g_kmax = sm[0];
}

// ---------------- per-batch selection (tier-aware, replicates reference) ------
__global__ __launch_bounds__(512)
void topk_kernel()
{
    __shared__ float sv[512];
    __shared__ int   si[512];
    __shared__ int   sfl[512];
    __shared__ int   sA[512];
    const int b = blockIdx.x, t = threadIdx.x;
    sv[t] = g_sv[b*512 + t];
    si[t] = t;
    __syncthreads();
    for (int k = 2; k <= 512; k <<= 1) {
        for (int j = k >> 1; j > 0; j >>= 1) {
            int ixj = t ^ j;
            if (ixj > t) {
                bool desc = ((t & k) == 0);
                float v1 = sv[t], v2 = sv[ixj];
                int   i1 = si[t], i2 = si[ixj];
                bool less = (v1 < v2) || (v1 == v2 && i1 > i2);
                bool sw = desc ? less : !less;
                if (sw) {
                    sv[t] = v2; sv[ixj] = v1;
                    si[t] = i2; si[ixj] = i1;
                }
            }
            __syncthreads();
        }
    }
    const int kmax = g_kmax;
    const int kper = g_kper[b];
    sfl[si[t]] = (t < kmax) ? 1 : 0;
    __syncthreads();
    const int sel   = sfl[t];
    const int tier2 = (int)g_tier2[b*512 + t];
    const int a1 = sel & (tier2 ^ 1);
    const int a2 = sel & tier2;
    sA[t] = a1 | (a2 << 16);
    __syncthreads();
    for (int off = 1; off < 512; off <<= 1) {
        int add = (t >= off) ? sA[t-off] : 0;
        __syncthreads();
        sA[t] += add;
        __syncthreads();
    }
    const int inc1 = sA[t] & 0xffff, inc2 = sA[t] >> 16;
    const int n1   = sA[511] & 0xffff;
    const int excl1 = inc1 - a1, excl2 = inc2 - a2;
    const int kept = (a1 && excl1 < kper) || (a2 && (n1 + excl2) < kper);
    const int nk = 1 - kept;
    __syncthreads();
    sA[t] = kept | (nk << 16);
    __syncthreads();
    for (int off = 1; off < 512; off <<= 1) {
        int add = (t >= off) ? sA[t-off] : 0;
        __syncthreads();
        sA[t] += add;
        __syncthreads();
    }
    const int rk = (sA[t] & 0xffff) - kept;
    const int rn = (sA[t] >> 16) - nk;
    if (kept) g_topk[b*512 + rk] = t;
    else      g_topk[b*512 + kper + rn] = t;
}

// ---------------- gather -> bf16 h_compact ------------------------------------
__global__ __launch_bounds__(64)
void gather_kernel(const float* __restrict__ x)
{
    int row = blockIdx.x;
    int b = row >> 9, j = row & 511;
    int t = threadIdx.x;
    uint2* dst = (uint2*)(g_hcb + (size_t)row * CC);
    if (j < g_kper[b]) {
        int src = g_topk[row];
        float4 v = ((const float4*)(x + ((size_t)b*512 + src) * CC))[t];
        uint2 o; o.x = pk(v.x, v.y); o.y = pk(v.z, v.w);
        dst[t] = o;
    } else {
        dst[t] = make_uint2(0u, 0u);
    }
}

// ---------------- flash attention v2 on HMMA (bf16 in, fp32 accum) ------------
#define QS 40   // Q/K smem stride (bf16)
#define VS 72   // Vt smem stride (bf16)
__global__ __launch_bounds__(128)
void attn_mma_kernel()
{
    __shared__ __align__(16) __nv_bfloat16 Qs[64*QS];
    __shared__ __align__(16) __nv_bfloat16 Ks[64*QS];
    __shared__ __align__(16) __nv_bfloat16 Vt[32*VS];
    const uint32_t qs_b = smem_u32(Qs);
    const uint32_t ks_b = smem_u32(Ks);
    const uint32_t vt_b = smem_u32(Vt);

    const int bh = blockIdx.x;
    const int b = bh >> 3, h = bh & 7;
    const int q0 = blockIdx.y << 6;
    const int tid = threadIdx.x;
    const int wid = tid >> 5, lane = tid & 31;
    const int kper = g_kper[b];
    const size_t base = (size_t)b * 512;
    const int hq = h * 32;

#pragma unroll
    for (int i = 0; i < 2; i++) {
        int idx = tid + i*128;
        int row = idx >> 2, qt = idx & 3;
        const uint4 v = *(const uint4*)(g_qkvb + (base + q0 + row) * 768 + hq + qt*8);
        *(uint4*)((char*)Qs + (row*QS + qt*8)*2) = v;
    }

    const uint32_t a_row = (uint32_t)(wid*16 + (lane & 15));
    const uint32_t a_kad = (uint32_t)((lane >> 4) << 3);
    const uint32_t b_rw  = (uint32_t)(((lane >> 4) << 3) + (lane & 7));
    const uint32_t b_kad = (uint32_t)(((lane >> 3) & 1) << 3);
    __syncthreads();
    uint32_t aq[2][4];
#pragma unroll
    for (int ks = 0; ks < 2; ks++)
        ldsm4(aq[ks][0], aq[ks][1], aq[ks][2], aq[ks][3],
              qs_b + (a_row*QS + ks*16 + a_kad)*2);

    float co[4][4];
#pragma unroll
    for (int i = 0; i < 4; i++)
#pragma unroll
        for (int j = 0; j < 4; j++) co[i][j] = 0.f;
    float m0 = -1e30f, m1 = -1e30f, l0 = 0.f, l1 = 0.f;
    const float scale = 0.17677669529663687f;
    const int colb = (lane & 3) << 1;

    for (int kt = 0; kt < kper; kt += 64) {
        __syncthreads();
#pragma unroll
        for (int i = 0; i < 2; i++) {
            int idx = tid + i*128;
            int row = idx >> 2, qt = idx & 3;
            int rk = min(kt + row, 511);
            const uint4 v = *(const uint4*)(g_qkvb + (base + rk) * 768 + 256 + hq + qt*8);
            *(uint4*)((char*)Ks + (row*QS + qt*8)*2) = v;
        }
#pragma unroll
        for (int i = 0; i < 4; i++) {
            int idx = tid + i*128;
            int key = idx >> 3, dg = (idx & 7) << 2;
            int rk = min(kt + key, 511);
            const uint2 v = *(const uint2*)(g_qkvb + (base + rk) * 768 + 512 + hq + dg);
            const __nv_bfloat16* pv = (const __nv_bfloat16*)&v;
            Vt[(dg+0)*VS + key] = pv[0];
            Vt[(dg+1)*VS + key] = pv[1];
            Vt[(dg+2)*VS + key] = pv[2];
            Vt[(dg+3)*VS + key] = pv[3];
        }
        __syncthreads();

        float cs[8][4];
#pragma unroll
        for (int nt = 0; nt < 8; nt++)
#pragma unroll
            for (int e = 0; e < 4; e++) cs[nt][e] = 0.f;
#pragma unroll
        for (int ks = 0; ks < 2; ks++) {
            uint32_t bk[8][2];
#pragma unroll
            for (int tp = 0; tp < 4; tp++) {
                uint32_t bd = ks_b + ((tp*16 + b_rw)*QS + ks*16 + b_kad)*2;
                ldsm4(bk[2*tp][0], bk[2*tp][1], bk[2*tp+1][0], bk[2*tp+1][1], bd);
            }
#pragma unroll
            for (int nt = 0; nt < 8; nt++)
                mma_bf16(cs[nt], aq[ks], bk[nt]);
        }
#pragma unroll
        for (int nt = 0; nt < 8; nt++) {
            int k0e = kt + nt*8 + colb;
#pragma unroll
            for (int e = 0; e < 4; e++) {
                float s = cs[nt][e] * scale;
                cs[nt][e] = (k0e + (e & 1) < kper) ? s : -1e30f;
            }
        }
        float mx0 = -1e30f, mx1 = -1e30f;
#pragma unroll
        for (int nt = 0; nt < 8; nt++) {
            mx0 = fmaxf(mx0, fmaxf(cs[nt][0], cs[nt][1]));
            mx1 = fmaxf(mx1, fmaxf(cs[nt][2], cs[nt][3]));
        }
        mx0 = fmaxf(mx0, __shfl_xor_sync(0xffffffffu, mx0, 1));
        mx0 = fmaxf(mx0, __shfl_xor_sync(0xffffffffu, mx0, 2));
        mx1 = fmaxf(mx1, __shfl_xor_sync(0xffffffffu, mx1, 1));
        mx1 = fmaxf(mx1, __shfl_xor_sync(0xffffffffu, mx1, 2));
        float mn0 = fmaxf(m0, mx0), mn1 = fmaxf(m1, mx1);
        float sf0 = __expf(m0 - mn0), sf1 = __expf(m1 - mn1);
        m0 = mn0; m1 = mn1;
        l0 *= sf0; l1 *= sf1;
#pragma unroll
        for (int nt = 0; nt < 4; nt++) {
            co[nt][0] *= sf0; co[nt][1] *= sf0;
            co[nt][2] *= sf1; co[nt][3] *= sf1;
        }
        uint32_t pa[4][4];
#pragma unroll
        for (int nt = 0; nt < 8; nt++) {
            float p0 = __expf(cs[nt][0] - m0);
            float p1 = __expf(cs[nt][1] - m0);
            float p2 = __expf(cs[nt][2] - m1);
            float p3 = __expf(cs[nt][3] - m1);
            l0 += p0 + p1; l1 += p2 + p3;
            int kc = nt >> 1, hi = (nt & 1) << 1;
            pa[kc][hi+0] = pk(p0, p1);
            pa[kc][hi+1] = pk(p2, p3);
        }
#pragma unroll
        for (int kc = 0; kc < 4; kc++) {
            uint32_t bv[4][2];
#pragma unroll
            for (int np = 0; np < 2; np++) {
                uint32_t vd = vt_b + ((np*16 + b_rw)*VS + kc*16 + b_kad)*2;
                ldsm4(bv[2*np][0], bv[2*np][1], bv[2*np+1][0], bv[2*np+1][1], vd);
            }
#pragma unroll
            for (int nt = 0; nt < 4; nt++)
                mma_bf16(co[nt], pa[kc], bv[nt]);
        }
    }
    l0 += __shfl_xor_sync(0xffffffffu, l0, 1);
    l0 += __shfl_xor_sync(0xffffffffu, l0, 2);
    l1 += __shfl_xor_sync(0xffffffffu, l1, 1);
    l1 += __shfl_xor_sync(0xffffffffu, l1, 2);
    float inv0 = 1.f / l0, inv1 = 1.f / l1;
    const int r0 = q0 + wid*16 + (lane >> 2);
#pragma unroll
    for (int nt = 0; nt < 4; nt++) {
        const int col = hq + nt*8 + colb;
        *(uint32_t*)(g_aob + (base + r0    ) * CC + col) = pk(co[nt][0]*inv0, co[nt][1]*inv0);
        *(uint32_t*)(g_aob + (base + r0 + 8) * CC + col) = pk(co[nt][2]*inv1, co[nt][3]*inv1);
    }
}

// ---------------- h = x * ratio (fp32 + bf16) ---------------------------------
__global__ __launch_bounds__(256)
void hbase_kernel(const float* __restrict__ x, const float* __restrict__ ratio)
{
    int i = blockIdx.x * 256 + threadIdx.x;   // float4 index
    int b = i >> 15;
    float r = ratio[b];
    float4 v = ((const float4*)x)[i];
    float4 o = make_float4(v.x*r, v.y*r, v.z*r, v.w*r);
    ((float4*)g_h)[i] = o;
    uint2 p; p.x = pk(o.x, o.y); p.y = pk(o.z, o.w);
    ((uint2*)g_hb)[i] = p;
}

// ------------------------------------------------------------------------------
extern "C" void kernel_launch(void* const* d_in, const int* in_sizes, int n_in,
                              void* d_out, int out_size)
{
    (void)in_sizes; (void)n_in; (void)out_size;
    const float* x      = (const float*)d_in[0];
    const float* ratio  = (const float*)d_in[3];
    const float* gumbel = (const float*)d_in[4];
    const float* Ws1    = (const float*)d_in[5];
    const float* bs1    = (const float*)d_in[6];
    const float* Ws2    = (const float*)d_in[7];
    const float* bs2    = (const float*)d_in[8];
    const float* Win    = (const float*)d_in[9];
    const float* b_in   = (const float*)d_in[10];
    const float* Wout   = (const float*)d_in[11];
    const float* bout   = (const float*)d_in[12];
    const float* Wm1    = (const float*)d_in[13];
    const float* bm1    = (const float*)d_in[14];
    const float* Wm2    = (const float*)d_in[15];
    const float* bm2    = (const float*)d_in[16];
    float* out = (float*)d_out;

    float *s1p, *hp;
    __nv_bfloat16 *qkvbp, *hcbp, *aobp, *hbp, *midbp, *winbp, *woutbp, *wm1bp, *wm2bp;
    cudaGetSymbolAddress((void**)&s1p,    g_s1);
    cudaGetSymbolAddress((void**)&hp,     g_h);
    cudaGetSymbolAddress((void**)&qkvbp,  g_qkvb);
    cudaGetSymbolAddress((void**)&hcbp,   g_hcb);
    cudaGetSymbolAddress((void**)&aobp,   g_aob);
    cudaGetSymbolAddress((void**)&hbp,    g_hb);
    cudaGetSymbolAddress((void**)&midbp,  g_midb);
    cudaGetSymbolAddress((void**)&winbp,  g_Winb);
    cudaGetSymbolAddress((void**)&woutbp, g_Woutb);
    cudaGetSymbolAddress((void**)&wm1bp,  g_Wm1b);
    cudaGetSymbolAddress((void**)&wm2bp,  g_Wm2b);

    // weight conversions (independent)
    f2bf_kernel<<<(3*CC*CC)/1024, 256>>>(Win,  winbp);
    f2bf_kernel<<<(CC*CC)/1024,   256>>>(Wout, woutbp);
    f2bf_kernel<<<(2*CC*CC)/1024, 256>>>(Wm1,  wm1bp);
    f2bf_kernel<<<(2*CC*CC)/1024, 256>>>(Wm2,  wm2bp);

    // 1. scorer (fp32, selection-critical — bit-faithful, do not touch)
    gemm_kernel<1,0><<<dim3(CC/128, NTOK/128), 256>>>(x, Ws1, bs1, nullptr, s1p, NTOK, CC, CC);
    score_kernel<<<NTOK/8, 256>>>(Ws2, bs2);
    softmax_kernel<<<BB, 512>>>(gumbel);
    kper_kernel<<<1, 64>>>(ratio);
    topk_kernel<<<BB, 512>>>();
    // 2. gather (bf16) + h base (must precede fused Wout-scatter)
    gather_kernel<<<NTOK, 64>>>(x);
    hbase_kernel<<<(NTOK*CC/4)/256, 256>>>(x, ratio);
    // 3. qkv = h_compact @ Win^T + b_in  (HMMA, bf16 out)
    wmma_gemm<0,0,1,0><<<dim3(6, NTOK/128), 256>>>(hcbp, winbp, b_in, nullptr,
                                                   nullptr, qkvbp, nullptr, NTOK, 3*CC, CC);
    // 4. attention (HMMA flash-attn, bf16 out)
    attn_mma_kernel<<<dim3(BB*HH, 8), 128>>>();
    // 5. Wout GEMM with fused scatter: h[topk] = (ao@Wout^T + bout + x)*ratio
    wmma_gemm<0,0,0,1><<<dim3(2, NTOK/128), 256>>>(aobp, woutbp, bout, x,
                                                   nullptr, nullptr, ratio, NTOK, CC, CC);
    // 6. mid = relu(h @ Wm1^T + bm1)  (bf16 out)
    wmma_gemm<1,0,1,0><<<dim3(4, NTOK/128), 256>>>(hbp, wm1bp, bm1, nullptr,
                                                   nullptr, midbp, nullptr, NTOK, 2*CC, CC);
    // 7. out = h + mid @ Wm2^T + bm2
    wmma_gemm<0,1,0,0><<<dim3(2, NTOK/128), 256>>>(midbp, wm2bp, bm2, hp,
                                                   out, nullptr, nullptr, NTOK, CC, 2*CC);
}

// round 14
// speedup vs baseline: 3.2820x; 1.0107x over previous
#include <cuda_runtime.h>
#include <cuda_bf16.h>
#include <math.h>
#include <stdint.h>

#define BB   64
#define LL   512
#define CC   256
#define HH   8
#define DHH  32
#define NTOK (BB*LL)

// ---------------- scratch (static __device__, no allocations) ----------------
__device__ float g_s1[(size_t)NTOK*CC];       // scorer hidden (fp32)
__device__ float g_z[BB*LL];                  // raw scores
__device__ float g_sv[BB*LL];                 // y_soft values (jax-replicated)
__device__ unsigned char g_tier2[BB*LL];      // token_mask residue flag
__device__ int   g_kper[BB];
__device__ int   g_kmax;
__device__ int   g_topk[BB*LL];
__device__ float g_h[(size_t)NTOK*CC];        // fp32 residual-scaled hidden
// bf16 operands for tensor-core GEMMs / attention
__device__ __nv_bfloat16 g_qkvb[(size_t)NTOK*3*CC];
__device__ __nv_bfloat16 g_hcb [(size_t)NTOK*CC];
__device__ __nv_bfloat16 g_aob [(size_t)NTOK*CC];
__device__ __nv_bfloat16 g_hb  [(size_t)NTOK*CC];
__device__ __nv_bfloat16 g_midb[(size_t)NTOK*2*CC];
__device__ __nv_bfloat16 g_Winb [3*CC*CC];
__device__ __nv_bfloat16 g_Woutb[CC*CC];
__device__ __nv_bfloat16 g_Wm1b [2*CC*CC];
__device__ __nv_bfloat16 g_Wm2b [CC*2*CC];

// ---------------- helpers -----------------------------------------------------
__device__ __forceinline__ uint32_t smem_u32(const void* p){
    uint32_t a;
    asm("{ .reg .u64 t; cvta.to.shared.u64 t, %1; cvt.u32.u64 %0, t; }" : "=r"(a) : "l"(p));
    return a;
}
__device__ __forceinline__ uint32_t pk(float a, float b){
    __nv_bfloat162 t = __floats2bfloat162_rn(a, b);
    return *reinterpret_cast<uint32_t*>(&t);
}
__device__ __forceinline__ void ldsm4(uint32_t& r0, uint32_t& r1, uint32_t& r2, uint32_t& r3,
                                      uint32_t addr){
    asm volatile("ldmatrix.sync.aligned.m8n8.x4.shared.b16 {%0,%1,%2,%3}, [%4];"
                 : "=r"(r0), "=r"(r1), "=r"(r2), "=r"(r3) : "r"(addr));
}
__device__ __forceinline__ void mma_bf16(float* c, const uint32_t* a, const uint32_t* b){
    asm volatile("mma.sync.aligned.m16n8k16.row.col.f32.bf16.bf16.f32 "
                 "{%0,%1,%2,%3}, {%4,%5,%6,%7}, {%8,%9}, {%0,%1,%2,%3};"
                 : "+f"(c[0]), "+f"(c[1]), "+f"(c[2]), "+f"(c[3])
                 : "r"(a[0]), "r"(a[1]), "r"(a[2]), "r"(a[3]), "r"(b[0]), "r"(b[1]));
}
__device__ __forceinline__ void cp16(uint32_t dst, const void* src){
    asm volatile("cp.async.cg.shared.global [%0], [%1], 16;" :: "r"(dst), "l"(src) : "memory");
}
#define CP_COMMIT() asm volatile("cp.async.commit_group;" ::: "memory")
#define CP_WAIT0()  asm volatile("cp.async.wait_group 0;"  ::: "memory")
// packed fp32x2 FMA (FFMA2) — two independent IEEE fp32 rn FMAs, bit-identical
__device__ __forceinline__ void ffma2(uint64_t& c, uint64_t a, uint64_t b){
    asm volatile("fma.rn.f32x2 %0, %1, %2, %0;" : "+l"(c) : "l"(a), "l"(b));
}
__device__ __forceinline__ uint64_t pk64(float lo, float hi){
    uint64_t v;
    asm("mov.b64 %0, {%1, %2};" : "=l"(v) : "f"(lo), "f"(hi));
    return v;
}
__device__ __forceinline__ void unpk64(float& lo, float& hi, uint64_t v){
    asm("mov.b64 {%0, %1}, %2;" : "=f"(lo), "=f"(hi) : "l"(v));
}

// ---------------- warp-MMA bf16 GEMM: out = act(A@W^T + bias) (+res/+scatter) -
#define SROW 40                      // smem row stride in bf16 (padded, 80B)
#define STAGEB (128*SROW*2)          // stage size in bytes (10240)

template<int ACT, int RES, int OUTBF, int SCAT>
__global__ __launch_bounds__(256)
void wmma_gemm(const __nv_bfloat16* __restrict__ A, const __nv_bfloat16* __restrict__ W,
               const float* __restrict__ bias, const float* __restrict__ res,
               float* __restrict__ outf, __nv_bfloat16* __restrict__ outb,
               const float* __restrict__ ratio,
               int M, int N, int K)
{
    __shared__ __align__(16) __nv_bfloat16 As[2*128*SROW];
    __shared__ __align__(16) __nv_bfloat16 Bs[2*128*SROW];
    const uint32_t as_b = smem_u32(As);
    const uint32_t bs_b = smem_u32(Bs);
    const int tid  = threadIdx.x;
    const int wid  = tid >> 5, lane = tid & 31;
    const int bm   = blockIdx.y << 7;
    const int bn   = blockIdx.x << 7;
    const int wm   = wid & 3;
    const int wn   = wid >> 2;

    const int lrow0 = (tid >> 2);          // 0..63
    const int lch   = (tid & 3) << 3;      // k offset 0,8,16,24
    const __nv_bfloat16* Ap0 = A + (size_t)(bm + lrow0     ) * K + lch;
    const __nv_bfloat16* Ap1 = A + (size_t)(bm + lrow0 + 64) * K + lch;
    const __nv_bfloat16* Wp0 = W + (size_t)(bn + lrow0     ) * K + lch;
    const __nv_bfloat16* Wp1 = W + (size_t)(bn + lrow0 + 64) * K + lch;
    const uint32_t soff0 = (uint32_t)(lrow0      * SROW + lch) * 2;
    const uint32_t soff1 = (uint32_t)((lrow0+64) * SROW + lch) * 2;

    const uint32_t a_row = (uint32_t)(wm*32 + (lane & 15));
    const uint32_t a_kad = (uint32_t)((lane >> 4) << 3);
    const uint32_t b_row = (uint32_t)(wn*64 + ((lane >> 4) << 3) + (lane & 7));
    const uint32_t b_kad = (uint32_t)(((lane >> 3) & 1) << 3);

    float acc[2][8][4];
#pragma unroll
    for (int i = 0; i < 2; i++)
#pragma unroll
        for (int j = 0; j < 8; j++)
#pragma unroll
            for (int q = 0; q < 4; q++) acc[i][j][q] = 0.f;

    const int nc = K >> 5;
    {
        cp16(as_b + soff0, Ap0); cp16(as_b + soff1, Ap1);
        cp16(bs_b + soff0, Wp0); cp16(bs_b + soff1, Wp1);
        CP_COMMIT();
    }

    for (int c = 0; c < nc; c++) {
        CP_WAIT0();
        __syncthreads();
        if (c + 1 < nc) {
            const int k1 = (c + 1) << 5;
            const uint32_t sb = ((c + 1) & 1) * STAGEB;
            cp16(as_b + sb + soff0, Ap0 + k1); cp16(as_b + sb + soff1, Ap1 + k1);
            cp16(bs_b + sb + soff0, Wp0 + k1); cp16(bs_b + sb + soff1, Wp1 + k1);
            CP_COMMIT();
        }
        const uint32_t ab = as_b + (c & 1) * STAGEB;
        const uint32_t bb = bs_b + (c & 1) * STAGEB;
#pragma unroll
        for (int ks = 0; ks < 2; ks++) {
            const uint32_t kcol = (uint32_t)(ks << 4);
            uint32_t a[2][4];
#pragma unroll
            for (int tm = 0; tm < 2; tm++) {
                uint32_t ad = ab + ((a_row + tm*16) * SROW + kcol + a_kad) * 2;
                ldsm4(a[tm][0], a[tm][1], a[tm][2], a[tm][3], ad);
            }
            uint32_t b[8][2];
#pragma unroll
            for (int tp = 0; tp < 4; tp++) {
                uint32_t bd = bb + ((b_row + tp*16) * SROW + kcol + b_kad) * 2;
                ldsm4(b[2*tp][0], b[2*tp][1], b[2*tp+1][0], b[2*tp+1][1], bd);
            }
#pragma unroll
            for (int tm = 0; tm < 2; tm++)
#pragma unroll
                for (int tn = 0; tn < 8; tn++)
                    mma_bf16(acc[tm][tn], a[tm], b[tn]);
        }
        __syncthreads();
    }

    if (SCAT) {
        const int kmax = g_kmax;
#pragma unroll
        for (int tm = 0; tm < 2; tm++) {
#pragma unroll
            for (int half = 0; half < 2; half++) {
                const int m = bm + wm*32 + tm*16 + (lane >> 2) + half*8;
                const int b = m >> 9, j = m & 511;
                if (j >= kmax) continue;
                const int dst = g_topk[m];
                const size_t node = (((size_t)b << 9) + dst) * CC;
                const float r = ratio[b];
#pragma unroll
                for (int tn = 0; tn < 8; tn++) {
                    const int gn = bn + wn*64 + tn*8 + ((lane & 3) << 1);
                    float v0 = acc[tm][tn][2*half+0] + bias[gn];
                    float v1 = acc[tm][tn][2*half+1] + bias[gn+1];
                    float2 xv = *(const float2*)(res + node + gn);
                    v0 = (v0 + xv.x) * r;
                    v1 = (v1 + xv.y) * r;
                    *(float2*)(g_h + node + gn) = make_float2(v0, v1);
                    *(uint32_t*)(g_hb + node + gn) = pk(v0, v1);
                }
            }
        }
        return;
    }

#pragma unroll
    for (int tm = 0; tm < 2; tm++) {
        const int gm = bm + wm*32 + tm*16 + (lane >> 2);
#pragma unroll
        for (int tn = 0; tn < 8; tn++) {
            const int gn = bn + wn*64 + tn*8 + ((lane & 3) << 1);
            const float b0 = bias[gn], b1 = bias[gn+1];
#pragma unroll
            for (int half = 0; half < 2; half++) {
                const int m = gm + half*8;
                float v0 = acc[tm][tn][2*half+0] + b0;
                float v1 = acc[tm][tn][2*half+1] + b1;
                if (ACT) { v0 = fmaxf(v0, 0.f); v1 = fmaxf(v1, 0.f); }
                const size_t o = (size_t)m * N + gn;
                if (RES) {
                    float2 r = *(const float2*)(res + o);
                    v0 += r.x; v1 += r.y;
                }
                if (OUTBF) *(uint32_t*)(outb + o) = pk(v0, v1);
                else       *(float2*)(outf + o)   = make_float2(v0, v1);
            }
        }
    }
}

// ---------------- fp32 SIMT GEMM (scorer only — selection-critical) ----------
// FFMA2 (fma.rn.f32x2) inner loop: bit-identical to scalar fmaf chain, half the
// fma-pipe instructions. Accumulation order per (i,j) unchanged.
template<int ACT>
__global__ __launch_bounds__(256)
void gemm_kernel(const float* __restrict__ A, const float* __restrict__ W,
                 const float* __restrict__ bias,
                 float* __restrict__ out, int M, int N, int K)
{
    __shared__ float As[8][132];
    __shared__ float Bs[8][132];
    const int tid = threadIdx.x;
    const int tx = tid & 15, ty = tid >> 4;
    const int bm = blockIdx.y << 7, bn = blockIdx.x << 7;
    const int lr = tid >> 1;
    const int lc = (tid & 1) << 2;

    uint64_t acc2[8][4];
#pragma unroll
    for (int i = 0; i < 8; i++)
#pragma unroll
        for (int j = 0; j < 4; j++) acc2[i][j] = 0ull;

    const float* Ap = A + (size_t)(bm + lr) * K + lc;
    const float* Wp = W + (size_t)(bn + lr) * K + lc;

    float4 av = *(const float4*)Ap;
    float4 wv = *(const float4*)Wp;

    for (int k0 = 0; k0 < K; k0 += 8) {
        __syncthreads();
        As[lc+0][lr]=av.x; As[lc+1][lr]=av.y; As[lc+2][lr]=av.z; As[lc+3][lr]=av.w;
        Bs[lc+0][lr]=wv.x; Bs[lc+1][lr]=wv.y; Bs[lc+2][lr]=wv.z; Bs[lc+3][lr]=wv.w;
        __syncthreads();
        if (k0 + 8 < K) {
            av = *(const float4*)(Ap + k0 + 8);
            wv = *(const float4*)(Wp + k0 + 8);
        }
#pragma unroll
        for (int kk = 0; kk < 8; kk++) {
            float a[8], b[8];
            *(float4*)&a[0] = *(const float4*)&As[kk][ty*8];
            *(float4*)&a[4] = *(const float4*)&As[kk][ty*8+4];
            *(float4*)&b[0] = *(const float4*)&Bs[kk][tx*8];
            *(float4*)&b[4] = *(const float4*)&Bs[kk][tx*8+4];
            uint64_t bp[4];
#pragma unroll
            for (int j = 0; j < 4; j++) bp[j] = pk64(b[2*j], b[2*j+1]);
#pragma unroll
            for (int i = 0; i < 8; i++) {
                const uint64_t ad = pk64(a[i], a[i]);
#pragma unroll
                for (int j = 0; j < 4; j++)
                    ffma2(acc2[i][j], ad, bp[j]);
            }
        }
    }

#pragma unroll
    for (int i = 0; i < 8; i++) {
        const size_t m = (size_t)bm + ty*8 + i;
#pragma unroll
        for (int j4 = 0; j4 < 2; j4++) {
            const int n = bn + tx*8 + j4*4;
            float c0, c1, c2, c3;
            unpk64(c0, c1, acc2[i][2*j4+0]);
            unpk64(c2, c3, acc2[i][2*j4+1]);
            float v[4] = {c0, c1, c2, c3};
#pragma unroll
            for (int j = 0; j < 4; j++) {
                float t = v[j] + bias[n+j];
                if (ACT) t = fmaxf(t, 0.f);
                v[j] = t;
            }
            *(float4*)(out + m*N + n) = make_float4(v[0],v[1],v[2],v[3]);
        }
    }
}

// ---------------- weights fp32 -> bf16, all four in one launch ----------------
// segments (in 1024-float4 blocks): Win 192, Wout 64, Wm1 128, Wm2 128 = 512
__global__ __launch_bounds__(256)
void f2bf4_kernel(const float* __restrict__ Win,  __nv_bfloat16* __restrict__ dWin,
                  const float* __restrict__ Wout, __nv_bfloat16* __restrict__ dWout,
                  const float* __restrict__ Wm1,  __nv_bfloat16* __restrict__ dWm1,
                  const float* __restrict__ Wm2,  __nv_bfloat16* __restrict__ dWm2)
{
    int blk = blockIdx.x;
    const float* s; __nv_bfloat16* d; int off;
    if      (blk < 192) { s = Win;  d = dWin;  off = blk;       }
    else if (blk < 256) { s = Wout; d = dWout; off = blk - 192; }
    else if (blk < 384) { s = Wm1;  d = dWm1;  off = blk - 256; }
    else                { s = Wm2;  d = dWm2;  off = blk - 384; }
    int i = off * 256 + threadIdx.x;
    float4 v = ((const float4*)s)[i];
    uint2 p; p.x = pk(v.x, v.y); p.y = pk(v.z, v.w);
    ((uint2*)d)[i] = p;
}

// ---------------- raw scores: z[n] = s1[n]·Ws2 + bs2 --------------------------
__global__ __launch_bounds__(256)
void score_kernel(const float* __restrict__ Ws2, const float* __restrict__ bs2)
{
    int gid  = blockIdx.x * 256 + threadIdx.x;
    int n    = gid >> 5;
    int lane = gid & 31;
    const float4* r4 = (const float4*)(g_s1 + (size_t)n * CC);
    const float4* w4 = (const float4*)Ws2;
    float4 a0 = r4[lane*2],   b0 = w4[lane*2];
    float4 a1 = r4[lane*2+1], b1 = w4[lane*2+1];
    float s = a0.x*b0.x + a0.y*b0.y + a0.z*b0.z + a0.w*b0.w
            + a1.x*b1.x + a1.y*b1.y + a1.z*b1.z + a1.w*b1.w;
#pragma unroll
    for (int o = 16; o; o >>= 1) s += __shfl_down_sync(0xffffffffu, s, o);
    if (lane == 0) g_z[n] = s + bs2[0];
}

// ---------------- jax-replicated softmax pipeline + tier flag -----------------
__global__ __launch_bounds__(512)
void softmax_kernel(const float* __restrict__ gumbel)
{
    __shared__ float red[512];
    const int b = blockIdx.x, t = threadIdx.x;
    const int n = b * 512 + t;
    float sc = g_z[n];

    red[t] = sc; __syncthreads();
#pragma unroll
    for (int s = 256; s; s >>= 1) { if (t < s) red[t] = fmaxf(red[t], red[t+s]); __syncthreads(); }
    float m1 = red[0]; __syncthreads();

    float sh = __fadd_rn(sc, -m1);
    float e1 = expf(sh);
    red[t] = e1; __syncthreads();
#pragma unroll
    for (int s = 256; s; s >>= 1) { if (t < s) red[t] = __fadd_rn(red[t], red[t+s]); __syncthreads(); }
    float L = logf(red[0]); __syncthreads();

    float ls = __fadd_rn(sh, -L);
    float z  = __fadd_rn(ls, gumbel[n]);
    red[t] = z; __syncthreads();
#pragma unroll
    for (int s = 256; s; s >>= 1) { if (t < s) red[t] = fmaxf(red[t], red[t+s]); __syncthreads(); }
    float m2 = red[0]; __syncthreads();

    float e2 = expf(__fadd_rn(z, -m2));
    red[t] = e2; __syncthreads();
#pragma unroll
    for (int s = 256; s; s >>= 1) { if (t < s) red[t] = __fadd_rn(red[t], red[t+s]); __syncthreads(); }
    float S = red[0];

    float sval = __fdiv_rn(e2, S);
    g_sv[n] = sval;
    float tt = __fadd_rn(__fadd_rn(1.0f, sval), -sval);
    g_tier2[n] = (tt != 1.0f) ? 1 : 0;
}

// ---------------- k_per / k_max ----------------------------------------------
__global__ void kper_kernel(const float* __restrict__ ratio)
{
    __shared__ int sm[64];
    int b = threadIdx.x;
    int kp = (int)ceilf(ratio[b] * 512.0f);
    if (kp < 1)  kp = 1;
    if (kp > LL) kp = LL;
    g_kper[b] = kp;
    sm[b] = kp;
    __syncthreads();
    for (int s = 32; s > 0; s >>= 1) {
        if (b < s) sm[b] = max(sm[b], sm[b+s]);
        __syncthreads();
    }
    if (b == 0) g_kmax = sm[0];
}

// ---------------- per-batch selection (tier-aware, replicates reference) ------
__global__ __launch_bounds__(512)
void topk_kernel()
{
    __shared__ float sv[512];
    __shared__ int   si[512];
    __shared__ int   sfl[512];
    __shared__ int   sA[512];
    const int b = blockIdx.x, t = threadIdx.x;
    sv[t] = g_sv[b*512 + t];
    si[t] = t;
    __syncthreads();
    for (int k = 2; k <= 512; k <<= 1) {
        for (int j = k >> 1; j > 0; j >>= 1) {
            int ixj = t ^ j;
            if (ixj > t) {
                bool desc = ((t & k) == 0);
                float v1 = sv[t], v2 = sv[ixj];
                int   i1 = si[t], i2 = si[ixj];
                bool less = (v1 < v2) || (v1 == v2 && i1 > i2);
                bool sw = desc ? less : !less;
                if (sw) {
                    sv[t] = v2; sv[ixj] = v1;
                    si[t] = i2; si[ixj] = i1;
                }
            }
            __syncthreads();
        }
    }
    const int kmax = g_kmax;
    const int kper = g_kper[b];
    sfl[si[t]] = (t < kmax) ? 1 : 0;
    __syncthreads();
    const int sel   = sfl[t];
    const int tier2 = (int)g_tier2[b*512 + t];
    const int a1 = sel & (tier2 ^ 1);
    const int a2 = sel & tier2;
    sA[t] = a1 | (a2 << 16);
    __syncthreads();
    for (int off = 1; off < 512; off <<= 1) {
        int add = (t >= off) ? sA[t-off] : 0;
        __syncthreads();
        sA[t] += add;
        __syncthreads();
    }
    const int inc1 = sA[t] & 0xffff, inc2 = sA[t] >> 16;
    const int n1   = sA[511] & 0xffff;
    const int excl1 = inc1 - a1, excl2 = inc2 - a2;
    const int kept = (a1 && excl1 < kper) || (a2 && (n1 + excl2) < kper);
    const int nk = 1 - kept;
    __syncthreads();
    sA[t] = kept | (nk << 16);
    __syncthreads();
    for (int off = 1; off < 512; off <<= 1) {
        int add = (t >= off) ? sA[t-off] : 0;
        __syncthreads();
        sA[t] += add;
        __syncthreads();
    }
    const int rk = (sA[t] & 0xffff) - kept;
    const int rn = (sA[t] >> 16) - nk;
    if (kept) g_topk[b*512 + rk] = t;
    else      g_topk[b*512 + kper + rn] = t;
}

// ---------------- gather -> bf16 h_compact ------------------------------------
__global__ __launch_bounds__(64)
void gather_kernel(const float* __restrict__ x)
{
    int row = blockIdx.x;
    int b = row >> 9, j = row & 511;
    int t = threadIdx.x;
    uint2* dst = (uint2*)(g_hcb + (size_t)row * CC);
    if (j < g_kper[b]) {
        int src = g_topk[row];
        float4 v = ((const float4*)(x + ((size_t)b*512 + src) * CC))[t];
        uint2 o; o.x = pk(v.x, v.y); o.y = pk(v.z, v.w);
        dst[t] = o;
    } else {
        dst[t] = make_uint2(0u, 0u);
    }
}

// ---------------- flash attention v2 on HMMA (bf16 in, fp32 accum) ------------
#define QS 40   // Q/K smem stride (bf16)
#define VS 72   // Vt smem stride (bf16)
__global__ __launch_bounds__(128)
void attn_mma_kernel()
{
    __shared__ __align__(16) __nv_bfloat16 Qs[64*QS];
    __shared__ __align__(16) __nv_bfloat16 Ks[64*QS];
    __shared__ __align__(16) __nv_bfloat16 Vt[32*VS];
    const uint32_t qs_b = smem_u32(Qs);
    const uint32_t ks_b = smem_u32(Ks);
    const uint32_t vt_b = smem_u32(Vt);

    const int bh = blockIdx.x;
    const int b = bh >> 3, h = bh & 7;
    const int q0 = blockIdx.y << 6;
    const int tid = threadIdx.x;
    const int wid = tid >> 5, lane = tid & 31;
    const int kper = g_kper[b];
    const size_t base = (size_t)b * 512;
    const int hq = h * 32;

#pragma unroll
    for (int i = 0; i < 2; i++) {
        int idx = tid + i*128;
        int row = idx >> 2, qt = idx & 3;
        const uint4 v = *(const uint4*)(g_qkvb + (base + q0 + row) * 768 + hq + qt*8);
        *(uint4*)((char*)Qs + (row*QS + qt*8)*2) = v;
    }

    const uint32_t a_row = (uint32_t)(wid*16 + (lane & 15));
    const uint32_t a_kad = (uint32_t)((lane >> 4) << 3);
    const uint32_t b_rw  = (uint32_t)(((lane >> 4) << 3) + (lane & 7));
    const uint32_t b_kad = (uint32_t)(((lane >> 3) & 1) << 3);
    __syncthreads();
    uint32_t aq[2][4];
#pragma unroll
    for (int ks = 0; ks < 2; ks++)
        ldsm4(aq[ks][0], aq[ks][1], aq[ks][2], aq[ks][3],
              qs_b + (a_row*QS + ks*16 + a_kad)*2);

    float co[4][4];
#pragma unroll
    for (int i = 0; i < 4; i++)
#pragma unroll
        for (int j = 0; j < 4; j++) co[i][j] = 0.f;
    float m0 = -1e30f, m1 = -1e30f, l0 = 0.f, l1 = 0.f;
    const float scale = 0.17677669529663687f;
    const int colb = (lane & 3) << 1;

    for (int kt = 0; kt < kper; kt += 64) {
        __syncthreads();
#pragma unroll
        for (int i = 0; i < 2; i++) {
            int idx = tid + i*128;
            int row = idx >> 2, qt = idx & 3;
            int rk = min(kt + row, 511);
            const uint4 v = *(const uint4*)(g_qkvb + (base + rk) * 768 + 256 + hq + qt*8);
            *(uint4*)((char*)Ks + (row*QS + qt*8)*2) = v;
        }
#pragma unroll
        for (int i = 0; i < 4; i++) {
            int idx = tid + i*128;
            int key = idx >> 3, dg = (idx & 7) << 2;
            int rk = min(kt + key, 511);
            const uint2 v = *(const uint2*)(g_qkvb + (base + rk) * 768 + 512 + hq + dg);
            const __nv_bfloat16* pv = (const __nv_bfloat16*)&v;
            Vt[(dg+0)*VS + key] = pv[0];
            Vt[(dg+1)*VS + key] = pv[1];
            Vt[(dg+2)*VS + key] = pv[2];
            Vt[(dg+3)*VS + key] = pv[3];
        }
        __syncthreads();

        float cs[8][4];
#pragma unroll
        for (int nt = 0; nt < 8; nt++)
#pragma unroll
            for (int e = 0; e < 4; e++) cs[nt][e] = 0.f;
#pragma unroll
        for (int ks = 0; ks < 2; ks++) {
            uint32_t bk[8][2];
#pragma unroll
            for (int tp = 0; tp < 4; tp++) {
                uint32_t bd = ks_b + ((tp*16 + b_rw)*QS + ks*16 + b_kad)*2;
                ldsm4(bk[2*tp][0], bk[2*tp][1], bk[2*tp+1][0], bk[2*tp+1][1], bd);
            }
#pragma unroll
            for (int nt = 0; nt < 8; nt++)
                mma_bf16(cs[nt], aq[ks], bk[nt]);
        }
#pragma unroll
        for (int nt = 0; nt < 8; nt++) {
            int k0e = kt + nt*8 + colb;
#pragma unroll
            for (int e = 0; e < 4; e++) {
                float s = cs[nt][e] * scale;
                cs[nt][e] = (k0e + (e & 1) < kper) ? s : -1e30f;
            }
        }
        float mx0 = -1e30f, mx1 = -1e30f;
#pragma unroll
        for (int nt = 0; nt < 8; nt++) {
            mx0 = fmaxf(mx0, fmaxf(cs[nt][0], cs[nt][1]));
            mx1 = fmaxf(mx1, fmaxf(cs[nt][2], cs[nt][3]));
        }
        mx0 = fmaxf(mx0, __shfl_xor_sync(0xffffffffu, mx0, 1));
        mx0 = fmaxf(mx0, __shfl_xor_sync(0xffffffffu, mx0, 2));
        mx1 = fmaxf(mx1, __shfl_xor_sync(0xffffffffu, mx1, 1));
        mx1 = fmaxf(mx1, __shfl_xor_sync(0xffffffffu, mx1, 2));
        float mn0 = fmaxf(m0, mx0), mn1 = fmaxf(m1, mx1);
        float sf0 = __expf(m0 - mn0), sf1 = __expf(m1 - mn1);
        m0 = mn0; m1 = mn1;
        l0 *= sf0; l1 *= sf1;
#pragma unroll
        for (int nt = 0; nt < 4; nt++) {
            co[nt][0] *= sf0; co[nt][1] *= sf0;
            co[nt][2] *= sf1; co[nt][3] *= sf1;
        }
        uint32_t pa[4][4];
#pragma unroll
        for (int nt = 0; nt < 8; nt++) {
            float p0 = __expf(cs[nt][0] - m0);
            float p1 = __expf(cs[nt][1] - m0);
            float p2 = __expf(cs[nt][2] - m1);
            float p3 = __expf(cs[nt][3] - m1);
            l0 += p0 + p1; l1 += p2 + p3;
            int kc = nt >> 1, hi = (nt & 1) << 1;
            pa[kc][hi+0] = pk(p0, p1);
            pa[kc][hi+1] = pk(p2, p3);
        }
#pragma unroll
        for (int kc = 0; kc < 4; kc++) {
            uint32_t bv[4][2];
#pragma unroll
            for (int np = 0; np < 2; np++) {
                uint32_t vd = vt_b + ((np*16 + b_rw)*VS + kc*16 + b_kad)*2;
                ldsm4(bv[2*np][0], bv[2*np][1], bv[2*np+1][0], bv[2*np+1][1], vd);
            }
#pragma unroll
            for (int nt = 0; nt < 4; nt++)
                mma_bf16(co[nt], pa[kc], bv[nt]);
        }
    }
    l0 += __shfl_xor_sync(0xffffffffu, l0, 1);
    l0 += __shfl_xor_sync(0xffffffffu, l0, 2);
    l1 += __shfl_xor_sync(0xffffffffu, l1, 1);
    l1 += __shfl_xor_sync(0xffffffffu, l1, 2);
    float inv0 = 1.f / l0, inv1 = 1.f / l1;
    const int r0 = q0 + wid*16 + (lane >> 2);
#pragma unroll
    for (int nt = 0; nt < 4; nt++) {
        const int col = hq + nt*8 + colb;
        *(uint32_t*)(g_aob + (base + r0    ) * CC + col) = pk(co[nt][0]*inv0, co[nt][1]*inv0);
        *(uint32_t*)(g_aob + (base + r0 + 8) * CC + col) = pk(co[nt][2]*inv1, co[nt][3]*inv1);
    }
}

// ---------------- h = x * ratio (fp32 + bf16) ---------------------------------
__global__ __launch_bounds__(256)
void hbase_kernel(const float* __restrict__ x, const float* __restrict__ ratio)
{
    int i = blockIdx.x * 256 + threadIdx.x;   // float4 index
    int b = i >> 15;
    float r = ratio[b];
    float4 v = ((const float4*)x)[i];
    float4 o = make_float4(v.x*r, v.y*r, v.z*r, v.w*r);
    ((float4*)g_h)[i] = o;
    uint2 p; p.x = pk(o.x, o.y); p.y = pk(o.z, o.w);
    ((uint2*)g_hb)[i] = p;
}

// ------------------------------------------------------------------------------
extern "C" void kernel_launch(void* const* d_in, const int* in_sizes, int n_in,
                              void* d_out, int out_size)
{
    (void)in_sizes; (void)n_in; (void)out_size;
    const float* x      = (const float*)d_in[0];
    const float* ratio  = (const float*)d_in[3];
    const float* gumbel = (const float*)d_in[4];
    const float* Ws1    = (const float*)d_in[5];
    const float* bs1    = (const float*)d_in[6];
    const float* Ws2    = (const float*)d_in[7];
    const float* bs2    = (const float*)d_in[8];
    const float* Win    = (const float*)d_in[9];
    const float* b_in   = (const float*)d_in[10];
    const float* Wout   = (const float*)d_in[11];
    const float* bout   = (const float*)d_in[12];
    const float* Wm1    = (const float*)d_in[13];
    const float* bm1    = (const float*)d_in[14];
    const float* Wm2    = (const float*)d_in[15];
    const float* bm2    = (const float*)d_in[16];
    float* out = (float*)d_out;

    float *s1p, *hp;
    __nv_bfloat16 *qkvbp, *hcbp, *aobp, *hbp, *midbp, *winbp, *woutbp, *wm1bp, *wm2bp;
    cudaGetSymbolAddress((void**)&s1p,    g_s1);
    cudaGetSymbolAddress((void**)&hp,     g_h);
    cudaGetSymbolAddress((void**)&qkvbp,  g_qkvb);
    cudaGetSymbolAddress((void**)&hcbp,   g_hcb);
    cudaGetSymbolAddress((void**)&aobp,   g_aob);
    cudaGetSymbolAddress((void**)&hbp,    g_hb);
    cudaGetSymbolAddress((void**)&midbp,  g_midb);
    cudaGetSymbolAddress((void**)&winbp,  g_Winb);
    cudaGetSymbolAddress((void**)&woutbp, g_Woutb);
    cudaGetSymbolAddress((void**)&wm1bp,  g_Wm1b);
    cudaGetSymbolAddress((void**)&wm2bp,  g_Wm2b);

    // weight conversions (single launch, 4 segments)
    f2bf4_kernel<<<512, 256>>>(Win, winbp, Wout, woutbp, Wm1, wm1bp, Wm2, wm2bp);

    // 1. scorer (fp32 FFMA2 — bit-identical to scalar fmaf chain)
    gemm_kernel<1><<<dim3(CC/128, NTOK/128), 256>>>(x, Ws1, bs1, s1p, NTOK, CC, CC);
    score_kernel<<<NTOK/8, 256>>>(Ws2, bs2);
    softmax_kernel<<<BB, 512>>>(gumbel);
    kper_kernel<<<1, 64>>>(ratio);
    topk_kernel<<<BB, 512>>>();
    // 2. gather (bf16) + h base (must precede fused Wout-scatter)
    gather_kernel<<<NTOK, 64>>>(x);
    hbase_kernel<<<(NTOK*CC/4)/256, 256>>>(x, ratio);
    // 3. qkv = h_compact @ Win^T + b_in  (HMMA, bf16 out)
    wmma_gemm<0,0,1,0><<<dim3(6, NTOK/128), 256>>>(hcbp, winbp, b_in, nullptr,
                                                   nullptr, qkvbp, nullptr, NTOK, 3*CC, CC);
    // 4. attention (HMMA flash-attn, bf16 out)
    attn_mma_kernel<<<dim3(BB*HH, 8), 128>>>();
    // 5. Wout GEMM with fused scatter: h[topk] = (ao@Wout^T + bout + x)*ratio
    wmma_gemm<0,0,0,1><<<dim3(2, NTOK/128), 256>>>(aobp, woutbp, bout, x,
                                                   nullptr, nullptr, ratio, NTOK, CC, CC);
    // 6. mid = relu(h @ Wm1^T + bm1)  (bf16 out)
    wmma_gemm<1,0,1,0><<<dim3(4, NTOK/128), 256>>>(hbp, wm1bp, bm1, nullptr,
                                                   nullptr, midbp, nullptr, NTOK, 2*CC, CC);
    // 7. out = h + mid @ Wm2^T + bm2
    wmma_gemm<0,1,0,0><<<dim3(2, NTOK/128), 256>>>(midbp, wm2bp, bm2, hp,
                                                   out, nullptr, nullptr, NTOK, CC, 2*CC);
}